// round 1
// baseline (speedup 1.0000x reference)
#include <cuda_runtime.h>
#include <math.h>

// ---------------- problem constants ----------------
#define NQ    200
#define NS    25
#define SEQL  8
#define DIN   2048
#define DOUT  1152
#define NTUP  56
#define WAYS  5
#define SHOTS 5
#define NTOT  (NS + NQ)        // 225
#define XROWS (NTOT * SEQL)    // 1800
#define SROWS (NS * NTUP)      // 1400 support tuple rows
#define QROWS (NQ * NTUP)      // 11200 query tuple rows
#define KROWS (NTOT * NTUP)    // 12600

#define SCALE_QK 0.029462782549439477f   // 1/sqrt(1152)

// ---------------- scratch (static device globals; no allocs) ----------------
__device__ float d_XP[XROWS * DIN];                 // inputs + positional enc
__device__ float d_Pk[XROWS * 3 * DOUT];            // x[l] @ Wk_block_j
__device__ float d_Pv[XROWS * 3 * DOUT];            // x[l] @ Wv_block_j
__device__ float d_K [KROWS * DOUT];                // LN(tuple K) : rows 0..1399 support, 1400.. query
__device__ float d_V [KROWS * DOUT];                // tuple V
__device__ float d_S [(size_t)QROWS * SROWS];       // scores -> attn (in place)

// combinations(range(8), 3) in lexicographic order
__constant__ int TUP[NTUP][3] = {
 {0,1,2},{0,1,3},{0,1,4},{0,1,5},{0,1,6},{0,1,7},
 {0,2,3},{0,2,4},{0,2,5},{0,2,6},{0,2,7},
 {0,3,4},{0,3,5},{0,3,6},{0,3,7},
 {0,4,5},{0,4,6},{0,4,7},
 {0,5,6},{0,5,7},
 {0,6,7},
 {1,2,3},{1,2,4},{1,2,5},{1,2,6},{1,2,7},
 {1,3,4},{1,3,5},{1,3,6},{1,3,7},
 {1,4,5},{1,4,6},{1,4,7},
 {1,5,6},{1,5,7},
 {1,6,7},
 {2,3,4},{2,3,5},{2,3,6},{2,3,7},
 {2,4,5},{2,4,6},{2,4,7},
 {2,5,6},{2,5,7},
 {2,6,7},
 {3,4,5},{3,4,6},{3,4,7},
 {3,5,6},{3,5,7},
 {3,6,7},
 {4,5,6},{4,5,7},{4,6,7},
 {5,6,7}
};

// ---------------- stage A: x + PE ----------------
__global__ void pe_add_kernel(const float* __restrict__ sup,
                              const float* __restrict__ qry) {
    int row = blockIdx.x;                 // 0..1799
    int i = row >> 3, l = row & 7;
    const float* src = (i < NS)
        ? sup + ((size_t)i * SEQL + l) * DIN
        : qry + ((size_t)(i - NS) * SEQL + l) * DIN;
    float* dst = d_XP + (size_t)row * DIN;
    const float kfac = -9.210340371976184f / (float)DIN;  // -ln(10000)/DIN
    for (int d = threadIdx.x; d < DIN; d += blockDim.x) {
        int k2 = d & ~1;                  // 2*(d/2)
        float arg = (float)l * expf((float)k2 * kfac);
        float pe = ((d & 1) ? cosf(arg) : sinf(arg)) * 0.1f;
        dst[d] = src[d] + pe;
    }
}

// ---------------- stage B: P = XP @ W_blocks (1800 x 2048 x 6912) ----------------
// gridDim = (9, 15, 6): z selects {Wk,Wv} x block j
__global__ void gemm_main(const float* __restrict__ Wk,
                          const float* __restrict__ Wv) {
    const int BM = 128, BN = 128, BK = 16;
    __shared__ float As[BK][BM];
    __shared__ float Bs[BK][BN];
    int z = blockIdx.z;
    int w = z / 3, j = z - w * 3;
    const float* __restrict__ B = (w ? Wv : Wk) + (size_t)j * DIN * DOUT;
    float* __restrict__ C = w ? d_Pv : d_Pk;

    int bm = blockIdx.y * BM, bn = blockIdx.x * BN;
    int tid = threadIdx.x;
    int tm = (tid >> 4) << 3;
    int tn = (tid & 15) << 3;
    int arow = tid >> 2, acol = (tid & 3) << 2;
    int brow = tid >> 5, bcol = (tid & 31) << 2;

    float acc[8][8];
#pragma unroll
    for (int a = 0; a < 8; a++)
#pragma unroll
        for (int b = 0; b < 8; b++) acc[a][b] = 0.f;

    for (int k0 = 0; k0 < DIN; k0 += BK) {
#pragma unroll
        for (int r = 0; r < 2; r++) {
            int row = arow + r * 64;
            int g = bm + row;
            float4 v = make_float4(0.f, 0.f, 0.f, 0.f);
            if (g < XROWS) v = *(const float4*)(&d_XP[(size_t)g * DIN + k0 + acol]);
            As[acol + 0][row] = v.x; As[acol + 1][row] = v.y;
            As[acol + 2][row] = v.z; As[acol + 3][row] = v.w;
        }
#pragma unroll
        for (int r = 0; r < 2; r++) {
            int kr = brow + r * 8;
            *(float4*)(&Bs[kr][bcol]) =
                *(const float4*)(&B[(size_t)(k0 + kr) * DOUT + bn + bcol]);
        }
        __syncthreads();
#pragma unroll
        for (int k = 0; k < BK; k++) {
            float4 a0 = *(const float4*)(&As[k][tm]);
            float4 a1 = *(const float4*)(&As[k][tm + 4]);
            float4 b0 = *(const float4*)(&Bs[k][tn]);
            float4 b1 = *(const float4*)(&Bs[k][tn + 4]);
            float av[8] = {a0.x, a0.y, a0.z, a0.w, a1.x, a1.y, a1.z, a1.w};
            float bv[8] = {b0.x, b0.y, b0.z, b0.w, b1.x, b1.y, b1.z, b1.w};
#pragma unroll
            for (int mi = 0; mi < 8; mi++)
#pragma unroll
                for (int ni = 0; ni < 8; ni++) acc[mi][ni] += av[mi] * bv[ni];
        }
        __syncthreads();
    }
#pragma unroll
    for (int mi = 0; mi < 8; mi++) {
        int g = bm + tm + mi;
        if (g < XROWS) {
            float* cp = &C[((size_t)g * 3 + j) * DOUT + bn + tn];
#pragma unroll
            for (int ni = 0; ni < 8; ni++) cp[ni] = acc[mi][ni];
        }
    }
}

// ---------------- stage C: tuple-sum + bias (+LN for K) ----------------
// grid = 12600 blocks of 128 threads (9 elems/thread, 1152 = 9*128)
__global__ void tuple_ln_kernel(const float* __restrict__ bk,
                                const float* __restrict__ bv,
                                const float* __restrict__ lnw,
                                const float* __restrict__ lnb) {
    int it = blockIdx.x;                  // 0..12599
    int i = it / NTUP, t = it - i * NTUP;
    int l0 = TUP[t][0], l1 = TUP[t][1], l2 = TUP[t][2];
    const float* pk0 = &d_Pk[((size_t)(i * SEQL + l0) * 3 + 0) * DOUT];
    const float* pk1 = &d_Pk[((size_t)(i * SEQL + l1) * 3 + 1) * DOUT];
    const float* pk2 = &d_Pk[((size_t)(i * SEQL + l2) * 3 + 2) * DOUT];
    const float* pv0 = &d_Pv[((size_t)(i * SEQL + l0) * 3 + 0) * DOUT];
    const float* pv1 = &d_Pv[((size_t)(i * SEQL + l1) * 3 + 1) * DOUT];
    const float* pv2 = &d_Pv[((size_t)(i * SEQL + l2) * 3 + 2) * DOUT];

    int tid = threadIdx.x;
    float kv[9];
    float s = 0.f, sq = 0.f;
#pragma unroll
    for (int e = 0; e < 9; e++) {
        int o = tid + e * 128;
        float v = pk0[o] + pk1[o] + pk2[o] + bk[o];
        kv[e] = v; s += v; sq += v * v;
        d_V[(size_t)it * DOUT + o] = pv0[o] + pv1[o] + pv2[o] + bv[o];
    }
#pragma unroll
    for (int o = 16; o; o >>= 1) {
        s  += __shfl_xor_sync(0xffffffffu, s,  o);
        sq += __shfl_xor_sync(0xffffffffu, sq, o);
    }
    __shared__ float ss[4], sqq[4];
    if ((tid & 31) == 0) { ss[tid >> 5] = s; sqq[tid >> 5] = sq; }
    __syncthreads();
    s  = ss[0] + ss[1] + ss[2] + ss[3];
    sq = sqq[0] + sqq[1] + sqq[2] + sqq[3];
    float mean = s * (1.0f / DOUT);
    float var  = sq * (1.0f / DOUT) - mean * mean;
    float rstd = rsqrtf(var + 1e-5f);
#pragma unroll
    for (int e = 0; e < 9; e++) {
        int o = tid + e * 128;
        d_K[(size_t)it * DOUT + o] = (kv[e] - mean) * rstd * lnw[o] + lnb[o];
    }
}

// ---------------- stage D: scores = scale * QK @ SK^T  (11200 x 1400 x 1152) ----------------
__global__ void gemm_scores() {
    const int BM = 128, BN = 128, BK = 16;
    __shared__ float As[BK][BM];
    __shared__ float Bs[BK][BN];
    const float* __restrict__ A  = d_K + (size_t)SROWS * DOUT;   // query rows
    const float* __restrict__ Bm = d_K;                          // support rows

    int bm = blockIdx.y * BM, bn = blockIdx.x * BN;
    int tid = threadIdx.x;
    int tm = (tid >> 4) << 3;
    int tn = (tid & 15) << 3;
    int arow = tid >> 2, acol = (tid & 3) << 2;

    float acc[8][8];
#pragma unroll
    for (int a = 0; a < 8; a++)
#pragma unroll
        for (int b = 0; b < 8; b++) acc[a][b] = 0.f;

    for (int k0 = 0; k0 < DOUT; k0 += BK) {
#pragma unroll
        for (int r = 0; r < 2; r++) {
            int row = arow + r * 64;
            int g = bm + row;
            float4 v = make_float4(0.f, 0.f, 0.f, 0.f);
            if (g < QROWS) v = *(const float4*)(&A[(size_t)g * DOUT + k0 + acol]);
            As[acol + 0][row] = v.x; As[acol + 1][row] = v.y;
            As[acol + 2][row] = v.z; As[acol + 3][row] = v.w;
            int gn = bn + row;
            float4 u = make_float4(0.f, 0.f, 0.f, 0.f);
            if (gn < SROWS) u = *(const float4*)(&Bm[(size_t)gn * DOUT + k0 + acol]);
            Bs[acol + 0][row] = u.x; Bs[acol + 1][row] = u.y;
            Bs[acol + 2][row] = u.z; Bs[acol + 3][row] = u.w;
        }
        __syncthreads();
#pragma unroll
        for (int k = 0; k < BK; k++) {
            float4 a0 = *(const float4*)(&As[k][tm]);
            float4 a1 = *(const float4*)(&As[k][tm + 4]);
            float4 b0 = *(const float4*)(&Bs[k][tn]);
            float4 b1 = *(const float4*)(&Bs[k][tn + 4]);
            float av[8] = {a0.x, a0.y, a0.z, a0.w, a1.x, a1.y, a1.z, a1.w};
            float bv[8] = {b0.x, b0.y, b0.z, b0.w, b1.x, b1.y, b1.z, b1.w};
#pragma unroll
            for (int mi = 0; mi < 8; mi++)
#pragma unroll
                for (int ni = 0; ni < 8; ni++) acc[mi][ni] += av[mi] * bv[ni];
        }
        __syncthreads();
    }
#pragma unroll
    for (int mi = 0; mi < 8; mi++) {
        int g = bm + tm + mi;
        if (g < QROWS) {
#pragma unroll
            for (int ni = 0; ni < 8; ni++) {
                int col = bn + tn + ni;
                if (col < SROWS)
                    d_S[(size_t)g * SROWS + col] = acc[mi][ni] * SCALE_QK;
            }
        }
    }
}

// ---------------- stage E: segmented softmax over 280 (shot x tuple) ----------------
// grid = (WAYS, QROWS), block = 128
__global__ void softmax_kernel() {
    int c = blockIdx.x;
    int m = blockIdx.y;
    float* p = d_S + (size_t)m * SROWS + c * (SHOTS * NTUP);
    int tid = threadIdx.x;
    float v[3];
    float mx = -3.4e38f;
#pragma unroll
    for (int e = 0; e < 3; e++) {
        int idx = tid + e * 128;
        if (idx < SHOTS * NTUP) { v[e] = p[idx]; mx = fmaxf(mx, v[e]); }
        else v[e] = -3.4e38f;
    }
#pragma unroll
    for (int o = 16; o; o >>= 1) mx = fmaxf(mx, __shfl_xor_sync(0xffffffffu, mx, o));
    __shared__ float sm[4];
    if ((tid & 31) == 0) sm[tid >> 5] = mx;
    __syncthreads();
    mx = fmaxf(fmaxf(sm[0], sm[1]), fmaxf(sm[2], sm[3]));

    float sum = 0.f;
#pragma unroll
    for (int e = 0; e < 3; e++) {
        int idx = tid + e * 128;
        if (idx < SHOTS * NTUP) { v[e] = expf(v[e] - mx); sum += v[e]; }
    }
#pragma unroll
    for (int o = 16; o; o >>= 1) sum += __shfl_xor_sync(0xffffffffu, sum, o);
    __shared__ float sq[4];
    if ((tid & 31) == 0) sq[tid >> 5] = sum;
    __syncthreads();
    sum = sq[0] + sq[1] + sq[2] + sq[3];
    float inv = 1.0f / sum;
#pragma unroll
    for (int e = 0; e < 3; e++) {
        int idx = tid + e * 128;
        if (idx < SHOTS * NTUP) p[idx] = v[e] * inv;
    }
}

// ---------------- stage F: fused proto + logits ----------------
// grid = (WAYS, NQ), block = (32, 8). Never materializes proto.
__global__ void proto_logits_kernel(float* __restrict__ out) {
    int c = blockIdx.x, q = blockIdx.y;
    int tx = threadIdx.x, ty = threadIdx.y;
    int tid = ty * 32 + tx;

    __shared__ float attn_s[NTUP * NTUP];   // [a][b] for one shot n
    __shared__ float cv_s[NTUP * 128];      // [b][dchunk]

    float total = 0.f;
    for (int d0 = 0; d0 < DOUT; d0 += 128) {          // 9 chunks
        float acc[7][4];
#pragma unroll
        for (int r = 0; r < 7; r++)
#pragma unroll
            for (int cc = 0; cc < 4; cc++) acc[r][cc] = 0.f;

        for (int n = 0; n < SHOTS; n++) {
            __syncthreads();
            for (int idx = tid; idx < NTUP * NTUP; idx += 256) {
                int a = idx / NTUP, b = idx - a * NTUP;
                attn_s[idx] = d_S[(size_t)(q * NTUP + a) * SROWS
                                  + c * (SHOTS * NTUP) + n * NTUP + b];
            }
            for (int idx = tid; idx < NTUP * 128; idx += 256) {
                int b = idx >> 7, dd = idx & 127;
                cv_s[idx] = d_V[((size_t)((c * SHOTS + n) * NTUP + b)) * DOUT + d0 + dd];
            }
            __syncthreads();
#pragma unroll 4
            for (int b = 0; b < NTUP; b++) {
                float bv4[4];
#pragma unroll
                for (int cc = 0; cc < 4; cc++) bv4[cc] = cv_s[b * 128 + tx + 32 * cc];
#pragma unroll
                for (int r = 0; r < 7; r++) {
                    float av = attn_s[(ty + 8 * r) * NTUP + b];
#pragma unroll
                    for (int cc = 0; cc < 4; cc++) acc[r][cc] += av * bv4[cc];
                }
            }
        }
        // accumulate ||qv - proto||^2 for this d-chunk
#pragma unroll
        for (int r = 0; r < 7; r++) {
            int a = ty + 8 * r;
            const float* qvp = &d_V[((size_t)((NS + q) * NTUP + a)) * DOUT + d0];
#pragma unroll
            for (int cc = 0; cc < 4; cc++) {
                float df = qvp[tx + 32 * cc] - acc[r][cc];
                total += df * df;
            }
        }
    }
#pragma unroll
    for (int o = 16; o; o >>= 1) total += __shfl_xor_sync(0xffffffffu, total, o);
    __shared__ float red[8];
    if (tx == 0) red[ty] = total;
    __syncthreads();
    if (tid == 0) {
        float s = 0.f;
#pragma unroll
        for (int i = 0; i < 8; i++) s += red[i];
        out[q * WAYS + c] = -s * (1.0f / (float)NTUP);
    }
}

// ---------------- launch ----------------
extern "C" void kernel_launch(void* const* d_in, const int* in_sizes, int n_in,
                              void* d_out, int out_size) {
    const float* sup = (const float*)d_in[0];
    const float* qry = (const float*)d_in[1];
    // d_in[2] = support_labels (int32) — layout is fixed class-grouped, unused
    const float* Wk  = (const float*)d_in[3];
    const float* bk  = (const float*)d_in[4];
    const float* Wv  = (const float*)d_in[5];
    const float* bv  = (const float*)d_in[6];
    const float* lnw = (const float*)d_in[7];
    const float* lnb = (const float*)d_in[8];
    float* out = (float*)d_out;

    pe_add_kernel<<<XROWS, 256>>>(sup, qry);

    dim3 g1(DOUT / 128, (XROWS + 127) / 128, 6);
    gemm_main<<<g1, 256>>>(Wk, Wv);

    tuple_ln_kernel<<<KROWS, 128>>>(bk, bv, lnw, lnb);

    dim3 g2((SROWS + 127) / 128, (QROWS + 127) / 128);
    gemm_scores<<<g2, 256>>>();

    dim3 g3(WAYS, QROWS);
    softmax_kernel<<<g3, 128>>>();

    dim3 g4(WAYS, NQ);
    dim3 b4(32, 8);
    proto_logits_kernel<<<g4, b4>>>(out);
}

// round 2
// speedup vs baseline: 2.7774x; 2.7774x over previous
#include <cuda_runtime.h>
#include <math.h>

// ---------------- problem constants ----------------
#define NQ    200
#define NS    25
#define SEQL  8
#define DIN   2048
#define DOUT  1152
#define NTUP  56
#define WAYS  5
#define SHOTS 5
#define NTOT  (NS + NQ)        // 225
#define XROWS (NTOT * SEQL)    // 1800
#define SROWS (NS * NTUP)      // 1400 support tuple rows
#define QROWS (NQ * NTUP)      // 11200 query tuple rows
#define KROWS (NTOT * NTUP)    // 12600

#define SCALE_QK 0.029462782549439477f   // 1/sqrt(1152)

// ---------------- scratch (static device globals; no allocs) ----------------
__device__ float d_XP[XROWS * DIN];
__device__ float d_Pk[XROWS * 3 * DOUT];
__device__ float d_Pv[XROWS * 3 * DOUT];
__device__ float d_K [KROWS * DOUT];
__device__ float d_V [KROWS * DOUT];
__device__ float d_S [(size_t)QROWS * SROWS];

__constant__ int TUP[NTUP][3] = {
 {0,1,2},{0,1,3},{0,1,4},{0,1,5},{0,1,6},{0,1,7},
 {0,2,3},{0,2,4},{0,2,5},{0,2,6},{0,2,7},
 {0,3,4},{0,3,5},{0,3,6},{0,3,7},
 {0,4,5},{0,4,6},{0,4,7},
 {0,5,6},{0,5,7},
 {0,6,7},
 {1,2,3},{1,2,4},{1,2,5},{1,2,6},{1,2,7},
 {1,3,4},{1,3,5},{1,3,6},{1,3,7},
 {1,4,5},{1,4,6},{1,4,7},
 {1,5,6},{1,5,7},
 {1,6,7},
 {2,3,4},{2,3,5},{2,3,6},{2,3,7},
 {2,4,5},{2,4,6},{2,4,7},
 {2,5,6},{2,5,7},
 {2,6,7},
 {3,4,5},{3,4,6},{3,4,7},
 {3,5,6},{3,5,7},
 {3,6,7},
 {4,5,6},{4,5,7},{4,6,7},
 {5,6,7}
};

// ---------------- tf32 helpers ----------------
__device__ __forceinline__ unsigned f2tf(float x) {
    unsigned r;
    asm("cvt.rna.tf32.f32 %0, %1;" : "=r"(r) : "f"(x));
    return r;
}

__device__ __forceinline__ void mma8(float* c, const unsigned* a, unsigned b0, unsigned b1) {
    asm volatile(
        "mma.sync.aligned.m16n8k8.row.col.f32.tf32.tf32.f32 "
        "{%0,%1,%2,%3}, {%4,%5,%6,%7}, {%8,%9}, {%0,%1,%2,%3};"
        : "+f"(c[0]), "+f"(c[1]), "+f"(c[2]), "+f"(c[3])
        : "r"(a[0]), "r"(a[1]), "r"(a[2]), "r"(a[3]), "r"(b0), "r"(b1));
}

// ---------------- stage A: x + PE ----------------
__global__ void pe_add_kernel(const float* __restrict__ sup,
                              const float* __restrict__ qry) {
    int row = blockIdx.x;
    int i = row >> 3, l = row & 7;
    const float* src = (i < NS)
        ? sup + ((size_t)i * SEQL + l) * DIN
        : qry + ((size_t)(i - NS) * SEQL + l) * DIN;
    float* dst = d_XP + (size_t)row * DIN;
    const float kfac = -9.210340371976184f / (float)DIN;
    for (int d = threadIdx.x; d < DIN; d += blockDim.x) {
        int k2 = d & ~1;
        float arg = (float)l * expf((float)k2 * kfac);
        float pe = ((d & 1) ? cosf(arg) : sinf(arg)) * 0.1f;
        dst[d] = src[d] + pe;
    }
}

// ---------------- stage B: P = XP @ W_blocks (tf32 tensor cores) ----------------
// grid (9, 15, 6); block 256 (8 warps, 2m x 4n), tile 128x128xBK16
__global__ void gemm_main_tc(const float* __restrict__ Wk,
                             const float* __restrict__ Wv) {
    __shared__ unsigned As[16][136];   // [k][m], stride%32==8 -> conflict-free frags
    __shared__ unsigned Bs[16][136];   // [k][n]
    int z = blockIdx.z;
    int w = z / 3, j = z - w * 3;
    const float* __restrict__ B = (w ? Wv : Wk) + (size_t)j * DIN * DOUT;
    float* __restrict__ C = w ? d_Pv : d_Pk;

    int bm = blockIdx.y * 128, bn = blockIdx.x * 128;
    int tid = threadIdx.x, lane = tid & 31, wid = tid >> 5;
    int wm = (wid & 1) * 64, wn = (wid >> 1) * 32;
    int lg = lane >> 2, lr = lane & 3;
    int ar = tid >> 2, ac = (tid & 3) << 2;     // A gmem: rows ar(+64), cols ac..ac+3
    int br = tid >> 5, bc = (tid & 31) << 2;    // B gmem: rows br(+8), cols bc..bc+3

    float acc[4][4][4];
#pragma unroll
    for (int mi = 0; mi < 4; mi++)
#pragma unroll
        for (int ni = 0; ni < 4; ni++)
#pragma unroll
            for (int e = 0; e < 4; e++) acc[mi][ni][e] = 0.f;

    for (int k0 = 0; k0 < DIN; k0 += 16) {
#pragma unroll
        for (int r = 0; r < 2; r++) {
            int row = ar + 64 * r;
            int g = bm + row;
            float4 v = make_float4(0.f, 0.f, 0.f, 0.f);
            if (g < XROWS) v = *(const float4*)(&d_XP[(size_t)g * DIN + k0 + ac]);
            As[ac + 0][row] = f2tf(v.x); As[ac + 1][row] = f2tf(v.y);
            As[ac + 2][row] = f2tf(v.z); As[ac + 3][row] = f2tf(v.w);
        }
#pragma unroll
        for (int r = 0; r < 2; r++) {
            int kr = br + 8 * r;
            float4 v = *(const float4*)(&B[(size_t)(k0 + kr) * DOUT + bn + bc]);
            Bs[kr][bc + 0] = f2tf(v.x); Bs[kr][bc + 1] = f2tf(v.y);
            Bs[kr][bc + 2] = f2tf(v.z); Bs[kr][bc + 3] = f2tf(v.w);
        }
        __syncthreads();
#pragma unroll
        for (int ks = 0; ks < 16; ks += 8) {
            unsigned af[4][4];
#pragma unroll
            for (int mi = 0; mi < 4; mi++) {
                int m = wm + mi * 16 + lg;
                af[mi][0] = As[ks + lr][m];
                af[mi][1] = As[ks + lr][m + 8];
                af[mi][2] = As[ks + lr + 4][m];
                af[mi][3] = As[ks + lr + 4][m + 8];
            }
#pragma unroll
            for (int ni = 0; ni < 4; ni++) {
                int n = wn + ni * 8 + lg;
                unsigned b0 = Bs[ks + lr][n];
                unsigned b1 = Bs[ks + lr + 4][n];
#pragma unroll
                for (int mi = 0; mi < 4; mi++)
                    mma8(acc[mi][ni], af[mi], b0, b1);
            }
        }
        __syncthreads();
    }
#pragma unroll
    for (int mi = 0; mi < 4; mi++) {
        int r0 = bm + wm + mi * 16 + lg;
        int r1 = r0 + 8;
#pragma unroll
        for (int ni = 0; ni < 4; ni++) {
            int cb = bn + wn + ni * 8 + lr * 2;
            if (r0 < XROWS) {
                float* p = &C[((size_t)r0 * 3 + j) * DOUT + cb];
                p[0] = acc[mi][ni][0]; p[1] = acc[mi][ni][1];
            }
            if (r1 < XROWS) {
                float* p = &C[((size_t)r1 * 3 + j) * DOUT + cb];
                p[0] = acc[mi][ni][2]; p[1] = acc[mi][ni][3];
            }
        }
    }
}

// ---------------- stage C: tuple-sum + bias (+LN for K) ----------------
__global__ void tuple_ln_kernel(const float* __restrict__ bk,
                                const float* __restrict__ bv,
                                const float* __restrict__ lnw,
                                const float* __restrict__ lnb) {
    int it = blockIdx.x;
    int i = it / NTUP, t = it - i * NTUP;
    int l0 = TUP[t][0], l1 = TUP[t][1], l2 = TUP[t][2];
    const float* pk0 = &d_Pk[((size_t)(i * SEQL + l0) * 3 + 0) * DOUT];
    const float* pk1 = &d_Pk[((size_t)(i * SEQL + l1) * 3 + 1) * DOUT];
    const float* pk2 = &d_Pk[((size_t)(i * SEQL + l2) * 3 + 2) * DOUT];
    const float* pv0 = &d_Pv[((size_t)(i * SEQL + l0) * 3 + 0) * DOUT];
    const float* pv1 = &d_Pv[((size_t)(i * SEQL + l1) * 3 + 1) * DOUT];
    const float* pv2 = &d_Pv[((size_t)(i * SEQL + l2) * 3 + 2) * DOUT];

    int tid = threadIdx.x;
    float kv[9];
    float s = 0.f, sq = 0.f;
#pragma unroll
    for (int e = 0; e < 9; e++) {
        int o = tid + e * 128;
        float v = pk0[o] + pk1[o] + pk2[o] + bk[o];
        kv[e] = v; s += v; sq += v * v;
        d_V[(size_t)it * DOUT + o] = pv0[o] + pv1[o] + pv2[o] + bv[o];
    }
#pragma unroll
    for (int o = 16; o; o >>= 1) {
        s  += __shfl_xor_sync(0xffffffffu, s,  o);
        sq += __shfl_xor_sync(0xffffffffu, sq, o);
    }
    __shared__ float ss[4], sqq[4];
    if ((tid & 31) == 0) { ss[tid >> 5] = s; sqq[tid >> 5] = sq; }
    __syncthreads();
    s  = ss[0] + ss[1] + ss[2] + ss[3];
    sq = sqq[0] + sqq[1] + sqq[2] + sqq[3];
    float mean = s * (1.0f / DOUT);
    float var  = sq * (1.0f / DOUT) - mean * mean;
    float rstd = rsqrtf(var + 1e-5f);
#pragma unroll
    for (int e = 0; e < 9; e++) {
        int o = tid + e * 128;
        d_K[(size_t)it * DOUT + o] = (kv[e] - mean) * rstd * lnw[o] + lnb[o];
    }
}

// ---------------- stage D: scores = scale * QK @ SK^T (tf32) ----------------
// grid (11, 88), block 256
__global__ void gemm_scores_tc() {
    __shared__ unsigned As[16][136];   // [k][m]  (query rows)
    __shared__ unsigned Bs[16][136];   // [k][n]  (support rows, transposed in)
    const float* __restrict__ A  = d_K + (size_t)SROWS * DOUT;
    const float* __restrict__ Bm = d_K;

    int bm = blockIdx.y * 128, bn = blockIdx.x * 128;
    int tid = threadIdx.x, lane = tid & 31, wid = tid >> 5;
    int wm = (wid & 1) * 64, wn = (wid >> 1) * 32;
    int lg = lane >> 2, lr = lane & 3;
    int ar = tid >> 2, ac = (tid & 3) << 2;

    float acc[4][4][4];
#pragma unroll
    for (int mi = 0; mi < 4; mi++)
#pragma unroll
        for (int ni = 0; ni < 4; ni++)
#pragma unroll
            for (int e = 0; e < 4; e++) acc[mi][ni][e] = 0.f;

    for (int k0 = 0; k0 < DOUT; k0 += 16) {
#pragma unroll
        for (int r = 0; r < 2; r++) {
            int row = ar + 64 * r;
            int g = bm + row;
            float4 v = make_float4(0.f, 0.f, 0.f, 0.f);
            if (g < QROWS) v = *(const float4*)(&A[(size_t)g * DOUT + k0 + ac]);
            As[ac + 0][row] = f2tf(v.x); As[ac + 1][row] = f2tf(v.y);
            As[ac + 2][row] = f2tf(v.z); As[ac + 3][row] = f2tf(v.w);
            int gn = bn + row;
            float4 u = make_float4(0.f, 0.f, 0.f, 0.f);
            if (gn < SROWS) u = *(const float4*)(&Bm[(size_t)gn * DOUT + k0 + ac]);
            Bs[ac + 0][row] = f2tf(u.x); Bs[ac + 1][row] = f2tf(u.y);
            Bs[ac + 2][row] = f2tf(u.z); Bs[ac + 3][row] = f2tf(u.w);
        }
        __syncthreads();
#pragma unroll
        for (int ks = 0; ks < 16; ks += 8) {
            unsigned af[4][4];
#pragma unroll
            for (int mi = 0; mi < 4; mi++) {
                int m = wm + mi * 16 + lg;
                af[mi][0] = As[ks + lr][m];
                af[mi][1] = As[ks + lr][m + 8];
                af[mi][2] = As[ks + lr + 4][m];
                af[mi][3] = As[ks + lr + 4][m + 8];
            }
#pragma unroll
            for (int ni = 0; ni < 4; ni++) {
                int n = wn + ni * 8 + lg;
                unsigned b0 = Bs[ks + lr][n];
                unsigned b1 = Bs[ks + lr + 4][n];
#pragma unroll
                for (int mi = 0; mi < 4; mi++)
                    mma8(acc[mi][ni], af[mi], b0, b1);
            }
        }
        __syncthreads();
    }
#pragma unroll
    for (int mi = 0; mi < 4; mi++) {
        int r0 = bm + wm + mi * 16 + lg;
        int r1 = r0 + 8;
#pragma unroll
        for (int ni = 0; ni < 4; ni++) {
            int cb = bn + wn + ni * 8 + lr * 2;
            if (cb < SROWS) {
                if (r0 < QROWS) {
                    float* p = &d_S[(size_t)r0 * SROWS + cb];
                    p[0] = acc[mi][ni][0] * SCALE_QK;
                    p[1] = acc[mi][ni][1] * SCALE_QK;
                }
                if (r1 < QROWS) {
                    float* p = &d_S[(size_t)r1 * SROWS + cb];
                    p[0] = acc[mi][ni][2] * SCALE_QK;
                    p[1] = acc[mi][ni][3] * SCALE_QK;
                }
            }
        }
    }
}

// ---------------- stage E: segmented softmax over 280 ----------------
__global__ void softmax_kernel() {
    int c = blockIdx.x;
    int m = blockIdx.y;
    float* p = d_S + (size_t)m * SROWS + c * (SHOTS * NTUP);
    int tid = threadIdx.x;
    float v[3];
    float mx = -3.4e38f;
#pragma unroll
    for (int e = 0; e < 3; e++) {
        int idx = tid + e * 128;
        if (idx < SHOTS * NTUP) { v[e] = p[idx]; mx = fmaxf(mx, v[e]); }
        else v[e] = -3.4e38f;
    }
#pragma unroll
    for (int o = 16; o; o >>= 1) mx = fmaxf(mx, __shfl_xor_sync(0xffffffffu, mx, o));
    __shared__ float sm[4];
    if ((tid & 31) == 0) sm[tid >> 5] = mx;
    __syncthreads();
    mx = fmaxf(fmaxf(sm[0], sm[1]), fmaxf(sm[2], sm[3]));

    float sum = 0.f;
#pragma unroll
    for (int e = 0; e < 3; e++) {
        int idx = tid + e * 128;
        if (idx < SHOTS * NTUP) { v[e] = expf(v[e] - mx); sum += v[e]; }
    }
#pragma unroll
    for (int o = 16; o; o >>= 1) sum += __shfl_xor_sync(0xffffffffu, sum, o);
    __shared__ float sq[4];
    if ((tid & 31) == 0) sq[tid >> 5] = sum;
    __syncthreads();
    sum = sq[0] + sq[1] + sq[2] + sq[3];
    float inv = 1.0f / sum;
#pragma unroll
    for (int e = 0; e < 3; e++) {
        int idx = tid + e * 128;
        if (idx < SHOTS * NTUP) p[idx] = v[e] * inv;
    }
}

// ---------------- stage F: fused proto + logits (tf32 tensor cores) ----------------
// grid (WAYS, NQ), block 256 (8 warps: 4m x 2n). Dynamic smem.
#define F_ATTN_STRIDE 292            // %32 == 4 -> conflict-free [m][k] frags
#define F_CV_STRIDE   136            // %32 == 8 -> conflict-free [k][n] frags
#define F_SMEM (64 * F_ATTN_STRIDE * 4 + 56 * F_CV_STRIDE * 4)

__global__ void proto_logits_tc(float* __restrict__ out) {
    extern __shared__ unsigned char smem_raw[];
    unsigned (*attn_s)[F_ATTN_STRIDE] = (unsigned(*)[F_ATTN_STRIDE])smem_raw;
    unsigned (*cv_s)[F_CV_STRIDE] =
        (unsigned(*)[F_CV_STRIDE])(smem_raw + 64 * F_ATTN_STRIDE * 4);

    int c = blockIdx.x, q = blockIdx.y;
    int tid = threadIdx.x, lane = tid & 31, wid = tid >> 5;
    int wm = (wid & 3) * 16, wn = (wid >> 2) * 64;
    int lg = lane >> 2, lr = lane & 3;

    // load attn [56 x 280] (rows 56..63 zero), convert to tf32
    for (int f4 = tid; f4 < 64 * 70; f4 += 256) {
        int a = f4 / 70, k4 = (f4 - a * 70) * 4;
        float4 v = make_float4(0.f, 0.f, 0.f, 0.f);
        if (a < NTUP)
            v = *(const float4*)(&d_S[(size_t)(q * NTUP + a) * SROWS + c * 280 + k4]);
        attn_s[a][k4 + 0] = f2tf(v.x); attn_s[a][k4 + 1] = f2tf(v.y);
        attn_s[a][k4 + 2] = f2tf(v.z); attn_s[a][k4 + 3] = f2tf(v.w);
    }

    float total = 0.f;
    for (int n0 = 0; n0 < DOUT; n0 += 128) {
        float acc[8][4];
#pragma unroll
        for (int ni = 0; ni < 8; ni++)
#pragma unroll
            for (int e = 0; e < 4; e++) acc[ni][e] = 0.f;

        for (int sh = 0; sh < SHOTS; sh++) {
            __syncthreads();
            for (int f4 = tid; f4 < 56 * 32; f4 += 256) {
                int kk = f4 >> 5, d4 = (f4 & 31) * 4;
                float4 v = *(const float4*)(
                    &d_V[(size_t)(c * 280 + sh * NTUP + kk) * DOUT + n0 + d4]);
                cv_s[kk][d4 + 0] = f2tf(v.x); cv_s[kk][d4 + 1] = f2tf(v.y);
                cv_s[kk][d4 + 2] = f2tf(v.z); cv_s[kk][d4 + 3] = f2tf(v.w);
            }
            __syncthreads();
#pragma unroll
            for (int ks = 0; ks < 7; ks++) {
                int kb = sh * NTUP + ks * 8;
                unsigned af[4];
                af[0] = attn_s[wm + lg][kb + lr];
                af[1] = attn_s[wm + lg + 8][kb + lr];
                af[2] = attn_s[wm + lg][kb + lr + 4];
                af[3] = attn_s[wm + lg + 8][kb + lr + 4];
#pragma unroll
                for (int ni = 0; ni < 8; ni++) {
                    int nn = wn + ni * 8 + lg;
                    unsigned b0 = cv_s[ks * 8 + lr][nn];
                    unsigned b1 = cv_s[ks * 8 + lr + 4][nn];
                    mma8(acc[ni], af, b0, b1);
                }
            }
        }
        // accumulate ||qv - proto||^2 for this n0 chunk
        int r0 = wm + lg, r1 = r0 + 8;
        const float* qv0 = &d_V[(size_t)((NS + q) * NTUP + r0) * DOUT];
        const float* qv1 = qv0 + (size_t)8 * DOUT;
#pragma unroll
        for (int ni = 0; ni < 8; ni++) {
            int col = n0 + wn + ni * 8 + lr * 2;
            if (r0 < NTUP) {
                float d0 = qv0[col]     - acc[ni][0];
                float d1 = qv0[col + 1] - acc[ni][1];
                total += d0 * d0 + d1 * d1;
            }
            if (r1 < NTUP) {
                float d2 = qv1[col]     - acc[ni][2];
                float d3 = qv1[col + 1] - acc[ni][3];
                total += d2 * d2 + d3 * d3;
            }
        }
    }
#pragma unroll
    for (int o = 16; o; o >>= 1) total += __shfl_xor_sync(0xffffffffu, total, o);
    __shared__ float red[8];
    if (lane == 0) red[wid] = total;
    __syncthreads();
    if (tid == 0) {
        float s = 0.f;
#pragma unroll
        for (int i = 0; i < 8; i++) s += red[i];
        out[q * WAYS + c] = -s * (1.0f / (float)NTUP);
    }
}

// ---------------- launch ----------------
extern "C" void kernel_launch(void* const* d_in, const int* in_sizes, int n_in,
                              void* d_out, int out_size) {
    const float* sup = (const float*)d_in[0];
    const float* qry = (const float*)d_in[1];
    const float* Wk  = (const float*)d_in[3];
    const float* bk  = (const float*)d_in[4];
    const float* Wv  = (const float*)d_in[5];
    const float* bv  = (const float*)d_in[6];
    const float* lnw = (const float*)d_in[7];
    const float* lnb = (const float*)d_in[8];
    float* out = (float*)d_out;

    cudaFuncSetAttribute(proto_logits_tc,
                         cudaFuncAttributeMaxDynamicSharedMemorySize, F_SMEM);

    pe_add_kernel<<<XROWS, 256>>>(sup, qry);

    dim3 g1(DOUT / 128, (XROWS + 127) / 128, 6);
    gemm_main_tc<<<g1, 256>>>(Wk, Wv);

    tuple_ln_kernel<<<KROWS, 128>>>(bk, bv, lnw, lnb);

    dim3 g2((SROWS + 127) / 128, (QROWS + 127) / 128);
    gemm_scores_tc<<<g2, 256>>>();

    dim3 g3(WAYS, QROWS);
    softmax_kernel<<<g3, 128>>>();

    dim3 g4(WAYS, NQ);
    proto_logits_tc<<<g4, 256, F_SMEM>>>(out);
}

// round 4
// speedup vs baseline: 3.4385x; 1.2380x over previous
#include <cuda_runtime.h>
#include <math.h>
#include <stdint.h>

// ---------------- problem constants ----------------
#define NQ    200
#define NS    25
#define SEQL  8
#define DIN   2048
#define DOUT  1152
#define NTUP  56
#define WAYS  5
#define SHOTS 5
#define NTOT  (NS + NQ)        // 225
#define XROWS (NTOT * SEQL)    // 1800
#define SROWS (NS * NTUP)      // 1400
#define QROWS (NQ * NTUP)      // 11200
#define KROWS (NTOT * NTUP)    // 12600

#define SCALE_QK 0.029462782549439477f   // 1/sqrt(1152)
#define WELEMS (DIN * 3 * DOUT)          // 7077888 per weight matrix

// ---------------- scratch ----------------
__device__ float d_XP[XROWS * DIN];                  // tf32-rounded
__device__ float d_Wkc[WELEMS];                      // tf32-rounded Wk
__device__ float d_Wvc[WELEMS];                      // tf32-rounded Wv
__device__ float d_Pk[XROWS * 3 * DOUT];
__device__ float d_Pv[XROWS * 3 * DOUT];
__device__ float d_K [KROWS * DOUT];                 // tf32-rounded (LN out)
__device__ float d_V [KROWS * DOUT];                 // fp32 (exact qv)
__device__ float d_Vt[KROWS * DOUT];                 // tf32-rounded (cv operand)
__device__ float d_S [(size_t)QROWS * SROWS];        // scores fp32 -> attn tf32-rounded

__constant__ int TUP[NTUP][3] = {
 {0,1,2},{0,1,3},{0,1,4},{0,1,5},{0,1,6},{0,1,7},
 {0,2,3},{0,2,4},{0,2,5},{0,2,6},{0,2,7},
 {0,3,4},{0,3,5},{0,3,6},{0,3,7},
 {0,4,5},{0,4,6},{0,4,7},
 {0,5,6},{0,5,7},
 {0,6,7},
 {1,2,3},{1,2,4},{1,2,5},{1,2,6},{1,2,7},
 {1,3,4},{1,3,5},{1,3,6},{1,3,7},
 {1,4,5},{1,4,6},{1,4,7},
 {1,5,6},{1,5,7},
 {1,6,7},
 {2,3,4},{2,3,5},{2,3,6},{2,3,7},
 {2,4,5},{2,4,6},{2,4,7},
 {2,5,6},{2,5,7},
 {2,6,7},
 {3,4,5},{3,4,6},{3,4,7},
 {3,5,6},{3,5,7},
 {3,6,7},
 {4,5,6},{4,5,7},{4,6,7},
 {5,6,7}
};

// ---------------- helpers ----------------
__device__ __forceinline__ float rna_tf32(float x) {
    unsigned r;
    asm("cvt.rna.tf32.f32 %0, %1;" : "=r"(r) : "f"(x));
    return __uint_as_float(r);
}

__device__ __forceinline__ void mma8(float* c, const unsigned* a, unsigned b0, unsigned b1) {
    asm volatile(
        "mma.sync.aligned.m16n8k8.row.col.f32.tf32.tf32.f32 "
        "{%0,%1,%2,%3}, {%4,%5,%6,%7}, {%8,%9}, {%0,%1,%2,%3};"
        : "+f"(c[0]), "+f"(c[1]), "+f"(c[2]), "+f"(c[3])
        : "r"(a[0]), "r"(a[1]), "r"(a[2]), "r"(a[3]), "r"(b0), "r"(b1));
}

__device__ __forceinline__ void cpa16(unsigned dst, const float* src, bool pred) {
    int sz = pred ? 16 : 0;
    asm volatile("cp.async.cg.shared.global [%0], [%1], 16, %2;\n"
                 :: "r"(dst), "l"(src), "r"(sz));
}
#define CP_COMMIT() asm volatile("cp.async.commit_group;\n")
#define CP_WAIT(n)  asm volatile("cp.async.wait_group %0;\n" :: "n"(n))

// ---------------- stage A0: pre-round weights to tf32 ----------------
__global__ void conv_w_kernel(const float* __restrict__ Wk,
                              const float* __restrict__ Wv) {
    int stride = gridDim.x * blockDim.x;
    for (int i = blockIdx.x * blockDim.x + threadIdx.x; i < WELEMS / 4; i += stride) {
        float4 a = ((const float4*)Wk)[i];
        a.x = rna_tf32(a.x); a.y = rna_tf32(a.y);
        a.z = rna_tf32(a.z); a.w = rna_tf32(a.w);
        ((float4*)d_Wkc)[i] = a;
        float4 b = ((const float4*)Wv)[i];
        b.x = rna_tf32(b.x); b.y = rna_tf32(b.y);
        b.z = rna_tf32(b.z); b.w = rna_tf32(b.w);
        ((float4*)d_Wvc)[i] = b;
    }
}

// ---------------- stage A: x + PE (tf32-rounded out) ----------------
__global__ void pe_add_kernel(const float* __restrict__ sup,
                              const float* __restrict__ qry) {
    int row = blockIdx.x;
    int i = row >> 3, l = row & 7;
    const float* src = (i < NS)
        ? sup + ((size_t)i * SEQL + l) * DIN
        : qry + ((size_t)(i - NS) * SEQL + l) * DIN;
    float* dst = d_XP + (size_t)row * DIN;
    const float kfac = -9.210340371976184f / (float)DIN;
    for (int d = threadIdx.x; d < DIN; d += blockDim.x) {
        int k2 = d & ~1;
        float arg = (float)l * expf((float)k2 * kfac);
        float pe = ((d & 1) ? cosf(arg) : sinf(arg)) * 0.1f;
        dst[d] = rna_tf32(src[d] + pe);
    }
}

// ---------------- stage B: P = XP @ W_blocks (tf32, cp.async 2-stage, BK=32) ----
#define MAIN_AS  (128 * 36)
#define MAIN_BS  (32 * 136)
#define MAIN_SMEM ((2 * MAIN_AS + 2 * MAIN_BS) * 4)

__global__ void gemm_main_tc() {
    extern __shared__ unsigned sh[];
    unsigned* As = sh;                        // [2][128][36]
    unsigned* Bs = sh + 2 * MAIN_AS;          // [2][32][136]
    unsigned as_base = (unsigned)__cvta_generic_to_shared(As);
    unsigned bs_base = (unsigned)__cvta_generic_to_shared(Bs);

    int z = blockIdx.z;
    int w = z / 3, j = z - w * 3;
    const float* __restrict__ Bp = (w ? d_Wvc : d_Wkc) + (size_t)j * DIN * DOUT;
    float* __restrict__ C = w ? d_Pv : d_Pk;

    int bm = blockIdx.y * 128, bn = blockIdx.x * 128;
    int tid = threadIdx.x, lane = tid & 31, wid = tid >> 5;
    int wm = (wid & 1) * 64, wn = (wid >> 1) * 32;
    int lg = lane >> 2, lr = lane & 3;

    float acc[4][4][4];
#pragma unroll
    for (int mi = 0; mi < 4; mi++)
#pragma unroll
        for (int ni = 0; ni < 4; ni++)
#pragma unroll
            for (int e = 0; e < 4; e++) acc[mi][ni][e] = 0.f;

    auto load_stage = [&](int s, int k0) {
#pragma unroll
        for (int i = 0; i < 4; i++) {
            int e = tid + i * 256;
            int ar = e >> 3, ac4 = (e & 7) * 4;
            bool pa = (bm + ar) < XROWS;
            const float* ga = d_XP + (size_t)(pa ? bm + ar : 0) * DIN + k0 + ac4;
            cpa16(as_base + (s * MAIN_AS + ar * 36 + ac4) * 4, ga, pa);
            int brr = e >> 5, bc4 = (e & 31) * 4;
            const float* gb = Bp + (size_t)(k0 + brr) * DOUT + bn + bc4;
            cpa16(bs_base + (s * MAIN_BS + brr * 136 + bc4) * 4, gb, true);
        }
    };

    const int KT = DIN / 32;   // 64
    load_stage(0, 0);
    CP_COMMIT();
    int buf = 0;
    for (int kt = 0; kt < KT; kt++) {
        if (kt + 1 < KT) {
            load_stage(buf ^ 1, (kt + 1) * 32);
            CP_COMMIT();
            CP_WAIT(1);
        } else {
            CP_WAIT(0);
        }
        __syncthreads();
        const unsigned* Aq = As + buf * MAIN_AS;
        const unsigned* Bq = Bs + buf * MAIN_BS;
#pragma unroll
        for (int ks = 0; ks < 4; ks++) {
            int kk = ks * 8;
            unsigned af[4][4];
#pragma unroll
            for (int mi = 0; mi < 4; mi++) {
                int m = wm + mi * 16 + lg;
                af[mi][0] = Aq[m * 36 + kk + lr];
                af[mi][1] = Aq[(m + 8) * 36 + kk + lr];
                af[mi][2] = Aq[m * 36 + kk + lr + 4];
                af[mi][3] = Aq[(m + 8) * 36 + kk + lr + 4];
            }
#pragma unroll
            for (int ni = 0; ni < 4; ni++) {
                int n = wn + ni * 8 + lg;
                unsigned b0 = Bq[(kk + lr) * 136 + n];
                unsigned b1 = Bq[(kk + lr + 4) * 136 + n];
#pragma unroll
                for (int mi = 0; mi < 4; mi++)
                    mma8(acc[mi][ni], af[mi], b0, b1);
            }
        }
        __syncthreads();
        buf ^= 1;
    }
#pragma unroll
    for (int mi = 0; mi < 4; mi++) {
        int r0 = bm + wm + mi * 16 + lg;
        int r1 = r0 + 8;
#pragma unroll
        for (int ni = 0; ni < 4; ni++) {
            int cb = bn + wn + ni * 8 + lr * 2;
            if (r0 < XROWS) {
                float* p = &C[((size_t)r0 * 3 + j) * DOUT + cb];
                p[0] = acc[mi][ni][0]; p[1] = acc[mi][ni][1];
            }
            if (r1 < XROWS) {
                float* p = &C[((size_t)r1 * 3 + j) * DOUT + cb];
                p[0] = acc[mi][ni][2]; p[1] = acc[mi][ni][3];
            }
        }
    }
}

// ---------------- stage C: tuple-sum + bias (+LN for K) ----------------
__global__ void tuple_ln_kernel(const float* __restrict__ bk,
                                const float* __restrict__ bv,
                                const float* __restrict__ lnw,
                                const float* __restrict__ lnb) {
    int it = blockIdx.x;
    int i = it / NTUP, t = it - i * NTUP;
    int l0 = TUP[t][0], l1 = TUP[t][1], l2 = TUP[t][2];
    const float* pk0 = &d_Pk[((size_t)(i * SEQL + l0) * 3 + 0) * DOUT];
    const float* pk1 = &d_Pk[((size_t)(i * SEQL + l1) * 3 + 1) * DOUT];
    const float* pk2 = &d_Pk[((size_t)(i * SEQL + l2) * 3 + 2) * DOUT];
    const float* pv0 = &d_Pv[((size_t)(i * SEQL + l0) * 3 + 0) * DOUT];
    const float* pv1 = &d_Pv[((size_t)(i * SEQL + l1) * 3 + 1) * DOUT];
    const float* pv2 = &d_Pv[((size_t)(i * SEQL + l2) * 3 + 2) * DOUT];

    int tid = threadIdx.x;
    float kv[9];
    float s = 0.f, sq = 0.f;
#pragma unroll
    for (int e = 0; e < 9; e++) {
        int o = tid + e * 128;
        float v = pk0[o] + pk1[o] + pk2[o] + bk[o];
        kv[e] = v; s += v; sq += v * v;
        float vv = pv0[o] + pv1[o] + pv2[o] + bv[o];
        d_V [(size_t)it * DOUT + o] = vv;
        d_Vt[(size_t)it * DOUT + o] = rna_tf32(vv);
    }
#pragma unroll
    for (int o = 16; o; o >>= 1) {
        s  += __shfl_xor_sync(0xffffffffu, s,  o);
        sq += __shfl_xor_sync(0xffffffffu, sq, o);
    }
    __shared__ float ss[4], sqq[4];
    if ((tid & 31) == 0) { ss[tid >> 5] = s; sqq[tid >> 5] = sq; }
    __syncthreads();
    s  = ss[0] + ss[1] + ss[2] + ss[3];
    sq = sqq[0] + sqq[1] + sqq[2] + sqq[3];
    float mean = s * (1.0f / DOUT);
    float var  = sq * (1.0f / DOUT) - mean * mean;
    float rstd = rsqrtf(var + 1e-5f);
#pragma unroll
    for (int e = 0; e < 9; e++) {
        int o = tid + e * 128;
        d_K[(size_t)it * DOUT + o] =
            rna_tf32((kv[e] - mean) * rstd * lnw[o] + lnb[o]);
    }
}

// ---------------- stage D: scores (tf32, cp.async 2-stage, BK=32) ----------------
#define SC_TS (128 * 36)
#define SC_SMEM (4 * SC_TS * 4)

__global__ void gemm_scores_tc() {
    extern __shared__ unsigned sh[];
    unsigned* As = sh;
    unsigned* Bs = sh + 2 * SC_TS;
    unsigned as_base = (unsigned)__cvta_generic_to_shared(As);
    unsigned bs_base = (unsigned)__cvta_generic_to_shared(Bs);

    const float* __restrict__ A  = d_K + (size_t)SROWS * DOUT;
    const float* __restrict__ Bm = d_K;

    int bm = blockIdx.y * 128, bn = blockIdx.x * 128;
    int tid = threadIdx.x, lane = tid & 31, wid = tid >> 5;
    int wm = (wid & 1) * 64, wn = (wid >> 1) * 32;
    int lg = lane >> 2, lr = lane & 3;

    float acc[4][4][4];
#pragma unroll
    for (int mi = 0; mi < 4; mi++)
#pragma unroll
        for (int ni = 0; ni < 4; ni++)
#pragma unroll
            for (int e = 0; e < 4; e++) acc[mi][ni][e] = 0.f;

    auto load_stage = [&](int s, int k0) {
#pragma unroll
        for (int i = 0; i < 4; i++) {
            int e = tid + i * 256;
            int row = e >> 3, c4 = (e & 7) * 4;
            bool pa = (bm + row) < QROWS;
            const float* ga = A + (size_t)(pa ? bm + row : 0) * DOUT + k0 + c4;
            cpa16(as_base + (s * SC_TS + row * 36 + c4) * 4, ga, pa);
            bool pb = (bn + row) < SROWS;
            const float* gb = Bm + (size_t)(pb ? bn + row : 0) * DOUT + k0 + c4;
            cpa16(bs_base + (s * SC_TS + row * 36 + c4) * 4, gb, pb);
        }
    };

    const int KT = DOUT / 32;   // 36
    load_stage(0, 0);
    CP_COMMIT();
    int buf = 0;
    for (int kt = 0; kt < KT; kt++) {
        if (kt + 1 < KT) {
            load_stage(buf ^ 1, (kt + 1) * 32);
            CP_COMMIT();
            CP_WAIT(1);
        } else {
            CP_WAIT(0);
        }
        __syncthreads();
        const unsigned* Aq = As + buf * SC_TS;
        const unsigned* Bq = Bs + buf * SC_TS;
#pragma unroll
        for (int ks = 0; ks < 4; ks++) {
            int kk = ks * 8;
            unsigned af[4][4];
#pragma unroll
            for (int mi = 0; mi < 4; mi++) {
                int m = wm + mi * 16 + lg;
                af[mi][0] = Aq[m * 36 + kk + lr];
                af[mi][1] = Aq[(m + 8) * 36 + kk + lr];
                af[mi][2] = Aq[m * 36 + kk + lr + 4];
                af[mi][3] = Aq[(m + 8) * 36 + kk + lr + 4];
            }
#pragma unroll
            for (int ni = 0; ni < 4; ni++) {
                int n = wn + ni * 8 + lg;
                unsigned b0 = Bq[n * 36 + kk + lr];
                unsigned b1 = Bq[n * 36 + kk + lr + 4];
#pragma unroll
                for (int mi = 0; mi < 4; mi++)
                    mma8(acc[mi][ni], af[mi], b0, b1);
            }
        }
        __syncthreads();
        buf ^= 1;
    }
#pragma unroll
    for (int mi = 0; mi < 4; mi++) {
        int r0 = bm + wm + mi * 16 + lg;
        int r1 = r0 + 8;
#pragma unroll
        for (int ni = 0; ni < 4; ni++) {
            int cb = bn + wn + ni * 8 + lr * 2;
            if (cb < SROWS) {
                if (r0 < QROWS) {
                    float* p = &d_S[(size_t)r0 * SROWS + cb];
                    p[0] = acc[mi][ni][0] * SCALE_QK;
                    p[1] = acc[mi][ni][1] * SCALE_QK;
                }
                if (r1 < QROWS) {
                    float* p = &d_S[(size_t)r1 * SROWS + cb];
                    p[0] = acc[mi][ni][2] * SCALE_QK;
                    p[1] = acc[mi][ni][3] * SCALE_QK;
                }
            }
        }
    }
}

// ---------------- stage E: segmented softmax over 280 (attn tf32-rounded out) ----
__global__ void softmax_kernel() {
    int c = blockIdx.x;
    int m = blockIdx.y;
    float* p = d_S + (size_t)m * SROWS + c * (SHOTS * NTUP);
    int tid = threadIdx.x;
    float v[3];
    float mx = -3.4e38f;
#pragma unroll
    for (int e = 0; e < 3; e++) {
        int idx = tid + e * 128;
        if (idx < SHOTS * NTUP) { v[e] = p[idx]; mx = fmaxf(mx, v[e]); }
        else v[e] = -3.4e38f;
    }
#pragma unroll
    for (int o = 16; o; o >>= 1) mx = fmaxf(mx, __shfl_xor_sync(0xffffffffu, mx, o));
    __shared__ float sm[4];
    if ((tid & 31) == 0) sm[tid >> 5] = mx;
    __syncthreads();
    mx = fmaxf(fmaxf(sm[0], sm[1]), fmaxf(sm[2], sm[3]));

    float sum = 0.f;
#pragma unroll
    for (int e = 0; e < 3; e++) {
        int idx = tid + e * 128;
        if (idx < SHOTS * NTUP) { v[e] = expf(v[e] - mx); sum += v[e]; }
    }
#pragma unroll
    for (int o = 16; o; o >>= 1) sum += __shfl_xor_sync(0xffffffffu, sum, o);
    __shared__ float sq[4];
    if ((tid & 31) == 0) sq[tid >> 5] = sum;
    __syncthreads();
    sum = sq[0] + sq[1] + sq[2] + sq[3];
    float inv = 1.0f / sum;
#pragma unroll
    for (int e = 0; e < 3; e++) {
        int idx = tid + e * 128;
        if (idx < SHOTS * NTUP) p[idx] = rna_tf32(v[e] * inv);
    }
}

// ---------------- stage F: fused proto + logits (tf32) ----------------
#define F_ATTN_STRIDE 292
#define F_CV_STRIDE   136
#define F_SMEM (64 * F_ATTN_STRIDE * 4 + 56 * F_CV_STRIDE * 4)

__global__ void proto_logits_tc(float* __restrict__ out) {
    extern __shared__ unsigned char smem_raw[];
    unsigned (*attn_s)[F_ATTN_STRIDE] = (unsigned(*)[F_ATTN_STRIDE])smem_raw;
    unsigned (*cv_s)[F_CV_STRIDE] =
        (unsigned(*)[F_CV_STRIDE])(smem_raw + 64 * F_ATTN_STRIDE * 4);

    int c = blockIdx.x, q = blockIdx.y;
    int tid = threadIdx.x, lane = tid & 31, wid = tid >> 5;
    int wm = (wid & 3) * 16, wn = (wid >> 2) * 64;
    int lg = lane >> 2, lr = lane & 3;

    // load attn [56 x 280] (already tf32-rounded; rows 56..63 zero)
    for (int f4 = tid; f4 < 64 * 70; f4 += 256) {
        int a = f4 / 70, k4 = (f4 - a * 70) * 4;
        float4 v = make_float4(0.f, 0.f, 0.f, 0.f);
        if (a < NTUP)
            v = *(const float4*)(&d_S[(size_t)(q * NTUP + a) * SROWS + c * 280 + k4]);
        *(float4*)(&attn_s[a][k4]) = v;
    }

    float total = 0.f;
    for (int n0 = 0; n0 < DOUT; n0 += 128) {
        float acc[8][4];
#pragma unroll
        for (int ni = 0; ni < 8; ni++)
#pragma unroll
            for (int e = 0; e < 4; e++) acc[ni][e] = 0.f;

        for (int sh = 0; sh < SHOTS; sh++) {
            __syncthreads();
            for (int f4 = tid; f4 < 56 * 32; f4 += 256) {
                int kk = f4 >> 5, d4 = (f4 & 31) * 4;
                *(float4*)(&cv_s[kk][d4]) = *(const float4*)(
                    &d_Vt[(size_t)(c * 280 + sh * NTUP + kk) * DOUT + n0 + d4]);
            }
            __syncthreads();
#pragma unroll
            for (int ks = 0; ks < 7; ks++) {
                int kb = sh * NTUP + ks * 8;
                unsigned af[4];
                af[0] = attn_s[wm + lg][kb + lr];
                af[1] = attn_s[wm + lg + 8][kb + lr];
                af[2] = attn_s[wm + lg][kb + lr + 4];
                af[3] = attn_s[wm + lg + 8][kb + lr + 4];
#pragma unroll
                for (int ni = 0; ni < 8; ni++) {
                    int nn = wn + ni * 8 + lg;
                    unsigned b0 = cv_s[ks * 8 + lr][nn];
                    unsigned b1 = cv_s[ks * 8 + lr + 4][nn];
                    mma8(acc[ni], af, b0, b1);
                }
            }
        }
        int r0 = wm + lg, r1 = r0 + 8;
        const float* qv0 = &d_V[(size_t)((NS + q) * NTUP + r0) * DOUT];
        const float* qv1 = qv0 + (size_t)8 * DOUT;
#pragma unroll
        for (int ni = 0; ni < 8; ni++) {
            int col = n0 + wn + ni * 8 + lr * 2;
            if (r0 < NTUP) {
                float d0 = qv0[col]     - acc[ni][0];
                float d1 = qv0[col + 1] - acc[ni][1];
                total += d0 * d0 + d1 * d1;
            }
            if (r1 < NTUP) {
                float d2 = qv1[col]     - acc[ni][2];
                float d3 = qv1[col + 1] - acc[ni][3];
                total += d2 * d2 + d3 * d3;
            }
        }
    }
#pragma unroll
    for (int o = 16; o; o >>= 1) total += __shfl_xor_sync(0xffffffffu, total, o);
    __shared__ float red[8];
    if (lane == 0) red[wid] = total;
    __syncthreads();
    if (tid == 0) {
        float s = 0.f;
#pragma unroll
        for (int i = 0; i < 8; i++) s += red[i];
        out[q * WAYS + c] = -s * (1.0f / (float)NTUP);
    }
}

// ---------------- launch ----------------
extern "C" void kernel_launch(void* const* d_in, const int* in_sizes, int n_in,
                              void* d_out, int out_size) {
    const float* sup = (const float*)d_in[0];
    const float* qry = (const float*)d_in[1];
    const float* Wk  = (const float*)d_in[3];
    const float* bk  = (const float*)d_in[4];
    const float* Wv  = (const float*)d_in[5];
    const float* bv  = (const float*)d_in[6];
    const float* lnw = (const float*)d_in[7];
    const float* lnb = (const float*)d_in[8];
    float* out = (float*)d_out;

    static int attr_done = 0;
    if (!attr_done) {
        cudaFuncSetAttribute(gemm_main_tc,
                             cudaFuncAttributeMaxDynamicSharedMemorySize, MAIN_SMEM);
        cudaFuncSetAttribute(gemm_scores_tc,
                             cudaFuncAttributeMaxDynamicSharedMemorySize, SC_SMEM);
        cudaFuncSetAttribute(proto_logits_tc,
                             cudaFuncAttributeMaxDynamicSharedMemorySize, F_SMEM);
        attr_done = 1;
    }

    conv_w_kernel<<<1024, 256>>>(Wk, Wv);
    pe_add_kernel<<<XROWS, 256>>>(sup, qry);

    dim3 g1(DOUT / 128, (XROWS + 127) / 128, 6);
    gemm_main_tc<<<g1, 256, MAIN_SMEM>>>();

    tuple_ln_kernel<<<KROWS, 128>>>(bk, bv, lnw, lnb);

    dim3 g2((SROWS + 127) / 128, (QROWS + 127) / 128);
    gemm_scores_tc<<<g2, 256, SC_SMEM>>>();

    dim3 g3(WAYS, QROWS);
    softmax_kernel<<<g3, 128>>>();

    dim3 g4(WAYS, NQ);
    proto_logits_tc<<<g4, 256, F_SMEM>>>(out);
}

// round 6
// speedup vs baseline: 6.2240x; 1.8101x over previous
#include <cuda_runtime.h>
#include <cuda_bf16.h>
#include <math.h>
#include <stdint.h>

// ---------------- problem constants ----------------
#define NQ    200
#define NS    25
#define SEQL  8
#define DIN   2048
#define DOUT  1152
#define NTUP  56
#define WAYS  5
#define SHOTS 5
#define NTOT  (NS + NQ)        // 225
#define XROWS (NTOT * SEQL)    // 1800
#define SROWS (NS * NTUP)      // 1400
#define QROWS (NQ * NTUP)      // 11200
#define KROWS (NTOT * NTUP)    // 12600

#define SCALE_QK 0.029462782549439477f   // 1/sqrt(1152)

// ---------------- scratch ----------------
__device__ __nv_bfloat16 d_XP[XROWS * DIN];                    // bf16(x + pe)
__device__ __nv_bfloat16 d_Wt[2 * 3 * DOUT * DIN];             // transposed bf16 weights [w][j][n][k]
__device__ float d_Pk[XROWS * 3 * DOUT];
__device__ float d_Pv[XROWS * 3 * DOUT];
__device__ __nv_bfloat16 d_K[KROWS * DOUT];                    // bf16 LN(K)
__device__ float d_V[KROWS * DOUT];                            // fp32 exact V
__device__ __nv_bfloat16 d_Vtt[WAYS * DOUT * 280];             // support V transposed [c][d][k]
__device__ float d_S[(size_t)QROWS * SROWS];                   // fp32 scores
__device__ __nv_bfloat16 d_At[(size_t)QROWS * WAYS * 320];     // bf16 attn, shot-padded 5*64

__constant__ int TUP[NTUP][3] = {
 {0,1,2},{0,1,3},{0,1,4},{0,1,5},{0,1,6},{0,1,7},
 {0,2,3},{0,2,4},{0,2,5},{0,2,6},{0,2,7},
 {0,3,4},{0,3,5},{0,3,6},{0,3,7},
 {0,4,5},{0,4,6},{0,4,7},
 {0,5,6},{0,5,7},
 {0,6,7},
 {1,2,3},{1,2,4},{1,2,5},{1,2,6},{1,2,7},
 {1,3,4},{1,3,5},{1,3,6},{1,3,7},
 {1,4,5},{1,4,6},{1,4,7},
 {1,5,6},{1,5,7},
 {1,6,7},
 {2,3,4},{2,3,5},{2,3,6},{2,3,7},
 {2,4,5},{2,4,6},{2,4,7},
 {2,5,6},{2,5,7},
 {2,6,7},
 {3,4,5},{3,4,6},{3,4,7},
 {3,5,6},{3,5,7},
 {3,6,7},
 {4,5,6},{4,5,7},{4,6,7},
 {5,6,7}
};

// ---------------- helpers ----------------
__device__ __forceinline__ void mma16(float* c, const unsigned* a, unsigned b0, unsigned b1) {
    asm volatile(
        "mma.sync.aligned.m16n8k16.row.col.f32.bf16.bf16.f32 "
        "{%0,%1,%2,%3}, {%4,%5,%6,%7}, {%8,%9}, {%0,%1,%2,%3};"
        : "+f"(c[0]), "+f"(c[1]), "+f"(c[2]), "+f"(c[3])
        : "r"(a[0]), "r"(a[1]), "r"(a[2]), "r"(a[3]), "r"(b0), "r"(b1));
}

__device__ __forceinline__ void cpa16(unsigned dst, const void* src, bool pred) {
    int sz = pred ? 16 : 0;
    asm volatile("cp.async.cg.shared.global [%0], [%1], 16, %2;\n"
                 :: "r"(dst), "l"(src), "r"(sz));
}
#define CP_COMMIT() asm volatile("cp.async.commit_group;\n")
#define CP_WAIT(n)  asm volatile("cp.async.wait_group %0;\n" :: "n"(n))

// ---------------- stage A0: transpose + convert W -> d_Wt [w][j][n][k] bf16 ----
// grid (64 ktiles, 36 ntiles, 6), block (32, 8)
__global__ void conv_wt_kernel(const float* __restrict__ Wk,
                               const float* __restrict__ Wv) {
    __shared__ float t[32][33];
    int z = blockIdx.z;
    int w = z / 3, j = z - w * 3;
    const float* __restrict__ W = w ? Wv : Wk;
    int k0 = blockIdx.x * 32, n0 = blockIdx.y * 32;
    int tx = threadIdx.x, ty = threadIdx.y;
#pragma unroll
    for (int r = 0; r < 4; r++) {
        int k = k0 + ty + r * 8;
        t[ty + r * 8][tx] = W[(size_t)(j * DIN + k) * DOUT + n0 + tx];
    }
    __syncthreads();
#pragma unroll
    for (int r = 0; r < 4; r++) {
        int n = n0 + ty + r * 8;
        d_Wt[((size_t)(w * 3 + j) * DOUT + n) * DIN + k0 + tx] =
            __float2bfloat16_rn(t[tx][ty + r * 8]);
    }
}

// ---------------- stage A: x + PE -> bf16 ----------------
__global__ void pe_add_kernel(const float* __restrict__ sup,
                              const float* __restrict__ qry) {
    int row = blockIdx.x;
    int i = row >> 3, l = row & 7;
    const float* src = (i < NS)
        ? sup + ((size_t)i * SEQL + l) * DIN
        : qry + ((size_t)(i - NS) * SEQL + l) * DIN;
    __nv_bfloat16* dst = d_XP + (size_t)row * DIN;
    const float kfac = -9.210340371976184f / (float)DIN;
    for (int d = threadIdx.x; d < DIN; d += blockDim.x) {
        int k2 = d & ~1;
        float arg = (float)l * expf((float)k2 * kfac);
        float pe = ((d & 1) ? cosf(arg) : sinf(arg)) * 0.1f;
        dst[d] = __float2bfloat16_rn(src[d] + pe);
    }
}

// ---------------- stage B: P = XP @ W_blocks (bf16 m16n8k16, BK=64, 2-stage) ----
// grid (9, 15, 6); block 256 (8 warps, 2m x 4n)
#define G_TS (128 * 36)                 // u32 words per stage per tile (pitch 72 bf16)
#define G_SMEM (4 * G_TS * 4)

__global__ void gemm_main_tc() {
    extern __shared__ unsigned sh[];
    unsigned* As = sh;                  // [2][128][36w]
    unsigned* Bs = sh + 2 * G_TS;       // [2][128][36w]
    unsigned as_base = (unsigned)__cvta_generic_to_shared(As);
    unsigned bs_base = (unsigned)__cvta_generic_to_shared(Bs);

    int z = blockIdx.z;
    int w = z / 3, j = z - w * 3;
    const __nv_bfloat16* __restrict__ Bp = d_Wt + (size_t)(w * 3 + j) * DOUT * DIN;
    float* __restrict__ C = w ? d_Pv : d_Pk;

    int bm = blockIdx.y * 128, bn = blockIdx.x * 128;
    int tid = threadIdx.x, lane = tid & 31, wid = tid >> 5;
    int wm = (wid & 1) * 64, wn = (wid >> 1) * 32;
    int lg = lane >> 2, lr = lane & 3;

    float acc[4][4][4];
#pragma unroll
    for (int mi = 0; mi < 4; mi++)
#pragma unroll
        for (int ni = 0; ni < 4; ni++)
#pragma unroll
            for (int e = 0; e < 4; e++) acc[mi][ni][e] = 0.f;

    auto load_stage = [&](int s, int k0) {
#pragma unroll
        for (int i = 0; i < 4; i++) {
            int e = tid + i * 256;
            int row = e >> 3, ch = e & 7;           // 8 x 16B chunks per row of 64 bf16
            bool pa = (bm + row) < XROWS;
            const __nv_bfloat16* ga =
                d_XP + (size_t)(pa ? bm + row : 0) * DIN + k0 + ch * 8;
            cpa16(as_base + (s * G_TS + row * 36 + ch * 4) * 4, ga, pa);
            const __nv_bfloat16* gb =
                Bp + (size_t)(bn + row) * DIN + k0 + ch * 8;
            cpa16(bs_base + (s * G_TS + row * 36 + ch * 4) * 4, gb, true);
        }
    };

    const int KT = DIN / 64;   // 32
    load_stage(0, 0);
    CP_COMMIT();
    int buf = 0;
    for (int kt = 0; kt < KT; kt++) {
        if (kt + 1 < KT) {
            load_stage(buf ^ 1, (kt + 1) * 64);
            CP_COMMIT();
            CP_WAIT(1);
        } else {
            CP_WAIT(0);
        }
        __syncthreads();
        const unsigned* Aq = As + buf * G_TS;
        const unsigned* Bq = Bs + buf * G_TS;
#pragma unroll
        for (int ks = 0; ks < 4; ks++) {          // k16 steps within 64
            int kw = ks * 8;                       // word offset
            unsigned af[4][4];
#pragma unroll
            for (int mi = 0; mi < 4; mi++) {
                int m = wm + mi * 16 + lg;
                af[mi][0] = Aq[m * 36 + kw + lr];
                af[mi][1] = Aq[(m + 8) * 36 + kw + lr];
                af[mi][2] = Aq[m * 36 + kw + lr + 4];
                af[mi][3] = Aq[(m + 8) * 36 + kw + lr + 4];
            }
#pragma unroll
            for (int ni = 0; ni < 4; ni++) {
                int n = wn + ni * 8 + lg;
                unsigned b0 = Bq[n * 36 + kw + lr];
                unsigned b1 = Bq[n * 36 + kw + lr + 4];
#pragma unroll
                for (int mi = 0; mi < 4; mi++)
                    mma16(acc[mi][ni], af[mi], b0, b1);
            }
        }
        __syncthreads();
        buf ^= 1;
    }
#pragma unroll
    for (int mi = 0; mi < 4; mi++) {
        int r0 = bm + wm + mi * 16 + lg;
        int r1 = r0 + 8;
#pragma unroll
        for (int ni = 0; ni < 4; ni++) {
            int cb = bn + wn + ni * 8 + lr * 2;
            if (r0 < XROWS) {
                float* p = &C[((size_t)r0 * 3 + j) * DOUT + cb];
                p[0] = acc[mi][ni][0]; p[1] = acc[mi][ni][1];
            }
            if (r1 < XROWS) {
                float* p = &C[((size_t)r1 * 3 + j) * DOUT + cb];
                p[0] = acc[mi][ni][2]; p[1] = acc[mi][ni][3];
            }
        }
    }
}

// ---------------- stage C: tuple-sum + bias (+LN for K) ----------------
__global__ void tuple_ln_kernel(const float* __restrict__ bk,
                                const float* __restrict__ bv,
                                const float* __restrict__ lnw,
                                const float* __restrict__ lnb) {
    int it = blockIdx.x;
    int i = it / NTUP, t = it - i * NTUP;
    int l0 = TUP[t][0], l1 = TUP[t][1], l2 = TUP[t][2];
    const float* pk0 = &d_Pk[((size_t)(i * SEQL + l0) * 3 + 0) * DOUT];
    const float* pk1 = &d_Pk[((size_t)(i * SEQL + l1) * 3 + 1) * DOUT];
    const float* pk2 = &d_Pk[((size_t)(i * SEQL + l2) * 3 + 2) * DOUT];
    const float* pv0 = &d_Pv[((size_t)(i * SEQL + l0) * 3 + 0) * DOUT];
    const float* pv1 = &d_Pv[((size_t)(i * SEQL + l1) * 3 + 1) * DOUT];
    const float* pv2 = &d_Pv[((size_t)(i * SEQL + l2) * 3 + 2) * DOUT];

    int tid = threadIdx.x;
    float kv[9];
    float s = 0.f, sq = 0.f;
#pragma unroll
    for (int e = 0; e < 9; e++) {
        int o = tid + e * 128;
        float v = pk0[o] + pk1[o] + pk2[o] + bk[o];
        kv[e] = v; s += v; sq += v * v;
        d_V[(size_t)it * DOUT + o] = pv0[o] + pv1[o] + pv2[o] + bv[o];
    }
#pragma unroll
    for (int o = 16; o; o >>= 1) {
        s  += __shfl_xor_sync(0xffffffffu, s,  o);
        sq += __shfl_xor_sync(0xffffffffu, sq, o);
    }
    __shared__ float ss[4], sqq[4];
    if ((tid & 31) == 0) { ss[tid >> 5] = s; sqq[tid >> 5] = sq; }
    __syncthreads();
    s  = ss[0] + ss[1] + ss[2] + ss[3];
    sq = sqq[0] + sqq[1] + sqq[2] + sqq[3];
    float mean = s * (1.0f / DOUT);
    float var  = sq * (1.0f / DOUT) - mean * mean;
    float rstd = rsqrtf(var + 1e-5f);
#pragma unroll
    for (int e = 0; e < 9; e++) {
        int o = tid + e * 128;
        d_K[(size_t)it * DOUT + o] =
            __float2bfloat16_rn((kv[e] - mean) * rstd * lnw[o] + lnb[o]);
    }
}

// ---------------- stage C2: transpose support V -> d_Vtt [c][d][k] bf16 ----------
// grid (9 ktiles, 36 dtiles, 5), block (32, 8)
__global__ void vtrans_kernel() {
    __shared__ float t[32][33];
    int c = blockIdx.z;
    int k0 = blockIdx.x * 32, d0 = blockIdx.y * 32;
    int tx = threadIdx.x, ty = threadIdx.y;
#pragma unroll
    for (int r = 0; r < 4; r++) {
        int kc = k0 + ty + r * 8;
        if (kc < 280)
            t[ty + r * 8][tx] = d_V[(size_t)(c * 280 + kc) * DOUT + d0 + tx];
    }
    __syncthreads();
#pragma unroll
    for (int r = 0; r < 4; r++) {
        int d = d0 + ty + r * 8;
        int kc = k0 + tx;
        if (kc < 280)
            d_Vtt[((size_t)c * DOUT + d) * 280 + kc] =
                __float2bfloat16_rn(t[tx][ty + r * 8]);
    }
}

// ---------------- stage D: scores (bf16 m16n8k16, BK=64, 2-stage) -------------
__global__ void gemm_scores_tc() {
    extern __shared__ unsigned sh[];
    unsigned* As = sh;
    unsigned* Bs = sh + 2 * G_TS;
    unsigned as_base = (unsigned)__cvta_generic_to_shared(As);
    unsigned bs_base = (unsigned)__cvta_generic_to_shared(Bs);

    const __nv_bfloat16* __restrict__ A  = d_K + (size_t)SROWS * DOUT;
    const __nv_bfloat16* __restrict__ Bm = d_K;

    int bm = blockIdx.y * 128, bn = blockIdx.x * 128;
    int tid = threadIdx.x, lane = tid & 31, wid = tid >> 5;
    int wm = (wid & 1) * 64, wn = (wid >> 1) * 32;
    int lg = lane >> 2, lr = lane & 3;

    float acc[4][4][4];
#pragma unroll
    for (int mi = 0; mi < 4; mi++)
#pragma unroll
        for (int ni = 0; ni < 4; ni++)
#pragma unroll
            for (int e = 0; e < 4; e++) acc[mi][ni][e] = 0.f;

    auto load_stage = [&](int s, int k0) {
#pragma unroll
        for (int i = 0; i < 4; i++) {
            int e = tid + i * 256;
            int row = e >> 3, ch = e & 7;
            bool pa = (bm + row) < QROWS;
            const __nv_bfloat16* ga =
                A + (size_t)(pa ? bm + row : 0) * DOUT + k0 + ch * 8;
            cpa16(as_base + (s * G_TS + row * 36 + ch * 4) * 4, ga, pa);
            bool pb = (bn + row) < SROWS;
            const __nv_bfloat16* gb =
                Bm + (size_t)(pb ? bn + row : 0) * DOUT + k0 + ch * 8;
            cpa16(bs_base + (s * G_TS + row * 36 + ch * 4) * 4, gb, pb);
        }
    };

    const int KT = DOUT / 64;   // 18
    load_stage(0, 0);
    CP_COMMIT();
    int buf = 0;
    for (int kt = 0; kt < KT; kt++) {
        if (kt + 1 < KT) {
            load_stage(buf ^ 1, (kt + 1) * 64);
            CP_COMMIT();
            CP_WAIT(1);
        } else {
            CP_WAIT(0);
        }
        __syncthreads();
        const unsigned* Aq = As + buf * G_TS;
        const unsigned* Bq = Bs + buf * G_TS;
#pragma unroll
        for (int ks = 0; ks < 4; ks++) {
            int kw = ks * 8;
            unsigned af[4][4];
#pragma unroll
            for (int mi = 0; mi < 4; mi++) {
                int m = wm + mi * 16 + lg;
                af[mi][0] = Aq[m * 36 + kw + lr];
                af[mi][1] = Aq[(m + 8) * 36 + kw + lr];
                af[mi][2] = Aq[m * 36 + kw + lr + 4];
                af[mi][3] = Aq[(m + 8) * 36 + kw + lr + 4];
            }
#pragma unroll
            for (int ni = 0; ni < 4; ni++) {
                int n = wn + ni * 8 + lg;
                unsigned b0 = Bq[n * 36 + kw + lr];
                unsigned b1 = Bq[n * 36 + kw + lr + 4];
#pragma unroll
                for (int mi = 0; mi < 4; mi++)
                    mma16(acc[mi][ni], af[mi], b0, b1);
            }
        }
        __syncthreads();
        buf ^= 1;
    }
#pragma unroll
    for (int mi = 0; mi < 4; mi++) {
        int r0 = bm + wm + mi * 16 + lg;
        int r1 = r0 + 8;
#pragma unroll
        for (int ni = 0; ni < 4; ni++) {
            int cb = bn + wn + ni * 8 + lr * 2;
            if (cb < SROWS) {
                if (r0 < QROWS) {
                    float* p = &d_S[(size_t)r0 * SROWS + cb];
                    p[0] = acc[mi][ni][0] * SCALE_QK;
                    p[1] = acc[mi][ni][1] * SCALE_QK;
                }
                if (r1 < QROWS) {
                    float* p = &d_S[(size_t)r1 * SROWS + cb];
                    p[0] = acc[mi][ni][2] * SCALE_QK;
                    p[1] = acc[mi][ni][3] * SCALE_QK;
                }
            }
        }
    }
}

// ---------------- stage E: segmented softmax -> bf16 shot-padded attn ----------
__global__ void softmax_kernel() {
    int c = blockIdx.x;
    int m = blockIdx.y;
    const float* p = d_S + (size_t)m * SROWS + c * (SHOTS * NTUP);
    __nv_bfloat16* po = d_At + ((size_t)m * WAYS + c) * 320;
    int tid = threadIdx.x;
    float v[3];
    float mx = -3.4e38f;
#pragma unroll
    for (int e = 0; e < 3; e++) {
        int idx = tid + e * 128;
        if (idx < SHOTS * NTUP) { v[e] = p[idx]; mx = fmaxf(mx, v[e]); }
        else v[e] = -3.4e38f;
    }
#pragma unroll
    for (int o = 16; o; o >>= 1) mx = fmaxf(mx, __shfl_xor_sync(0xffffffffu, mx, o));
    __shared__ float sm[4];
    if ((tid & 31) == 0) sm[tid >> 5] = mx;
    __syncthreads();
    mx = fmaxf(fmaxf(sm[0], sm[1]), fmaxf(sm[2], sm[3]));

    float sum = 0.f;
#pragma unroll
    for (int e = 0; e < 3; e++) {
        int idx = tid + e * 128;
        if (idx < SHOTS * NTUP) { v[e] = expf(v[e] - mx); sum += v[e]; }
    }
#pragma unroll
    for (int o = 16; o; o >>= 1) sum += __shfl_xor_sync(0xffffffffu, sum, o);
    __shared__ float sq[4];
    if ((tid & 31) == 0) sq[tid >> 5] = sum;
    __syncthreads();
    sum = sq[0] + sq[1] + sq[2] + sq[3];
    float inv = 1.0f / sum;
#pragma unroll
    for (int e = 0; e < 3; e++) {
        int idx = tid + e * 128;
        if (idx < SHOTS * NTUP) {
            int shd = idx / NTUP, t = idx - shd * NTUP;
            po[shd * 64 + t] = __float2bfloat16_rn(v[e] * inv);
        } else if (idx < 320) {
            int p2 = idx - 280;
            po[(p2 >> 3) * 64 + 56 + (p2 & 7)] = __float2bfloat16_rn(0.f);
        }
    }
}

// ---------------- stage F: fused proto + logits (bf16 m16n8k16) ---------------
// grid (WAYS, NQ), block 256 (8 warps: 4m x 2n)
#define F_ATTN_PW 164                  // u32 words per attn row (pitch 328 bf16)
#define F_CV_PW   36                   // u32 words per cv row (pitch 72 bf16)
#define F_SMEM (64 * F_ATTN_PW * 4 + 128 * F_CV_PW * 4)

__global__ void proto_logits_tc(float* __restrict__ out) {
    extern __shared__ unsigned char smem_raw[];
    unsigned* attn_w = (unsigned*)smem_raw;
    unsigned* cv_w = (unsigned*)(smem_raw + 64 * F_ATTN_PW * 4);
    unsigned attn_base = (unsigned)__cvta_generic_to_shared(attn_w);
    unsigned cv_base = (unsigned)__cvta_generic_to_shared(cv_w);

    int c = blockIdx.x, q = blockIdx.y;
    int tid = threadIdx.x, lane = tid & 31, wid = tid >> 5;
    int wm = (wid & 3) * 16, wn = (wid >> 2) * 64;
    int lg = lane >> 2, lr = lane & 3;

    // zero cv tile (tail k 56..63 + pad stays zero forever)
    for (int wi = tid; wi < 128 * F_CV_PW; wi += 256) cv_w[wi] = 0u;

    // load attn [56 x 320] bf16 shot-padded; rows 56..63 zero
    for (int f = tid; f < 64 * 40; f += 256) {
        int a = f / 40, ch = f - a * 40;
        if (a < NTUP) {
            const __nv_bfloat16* src =
                d_At + ((size_t)(q * NTUP + a) * WAYS + c) * 320 + ch * 8;
            cpa16(attn_base + a * 656 + ch * 16, src, true);
        } else {
            *(uint4*)(smem_raw + a * 656 + ch * 16) = make_uint4(0, 0, 0, 0);
        }
    }
    CP_COMMIT();
    CP_WAIT(0);
    __syncthreads();

    float total = 0.f;
    for (int n0 = 0; n0 < DOUT; n0 += 128) {
        float acc[8][4];
#pragma unroll
        for (int ni = 0; ni < 8; ni++)
#pragma unroll
            for (int e = 0; e < 4; e++) acc[ni][e] = 0.f;

        for (int shd = 0; shd < SHOTS; shd++) {
            __syncthreads();
            // cv tile: rows n (=d), cols k 0..55 from d_Vtt
            for (int f = tid; f < 128 * 7; f += 256) {
                int n = f / 7, ch = f - n * 7;
                const __nv_bfloat16* src =
                    d_Vtt + ((size_t)c * DOUT + n0 + n) * 280 + shd * 56 + ch * 8;
                cpa16(cv_base + n * 144 + ch * 16, src, true);
            }
            CP_COMMIT();
            CP_WAIT(0);
            __syncthreads();
#pragma unroll
            for (int ks = 0; ks < 4; ks++) {
                int aw = shd * 32 + ks * 8;       // word offset into attn row
                unsigned af[4];
                af[0] = attn_w[(wm + lg) * F_ATTN_PW + aw + lr];
                af[1] = attn_w[(wm + lg + 8) * F_ATTN_PW + aw + lr];
                af[2] = attn_w[(wm + lg) * F_ATTN_PW + aw + lr + 4];
                af[3] = attn_w[(wm + lg + 8) * F_ATTN_PW + aw + lr + 4];
#pragma unroll
                for (int ni = 0; ni < 8; ni++) {
                    int nn = wn + ni * 8 + lg;
                    unsigned b0 = cv_w[nn * F_CV_PW + ks * 8 + lr];
                    unsigned b1 = cv_w[nn * F_CV_PW + ks * 8 + lr + 4];
                    mma16(acc[ni], af, b0, b1);
                }
            }
        }
        int r0 = wm + lg, r1 = r0 + 8;
        const float* qv0 = &d_V[(size_t)((NS + q) * NTUP + r0) * DOUT];
        const float* qv1 = qv0 + (size_t)8 * DOUT;
#pragma unroll
        for (int ni = 0; ni < 8; ni++) {
            int col = n0 + wn + ni * 8 + lr * 2;
            if (r0 < NTUP) {
                float d0 = qv0[col]     - acc[ni][0];
                float d1 = qv0[col + 1] - acc[ni][1];
                total += d0 * d0 + d1 * d1;
            }
            if (r1 < NTUP) {
                float d2 = qv1[col]     - acc[ni][2];
                float d3 = qv1[col + 1] - acc[ni][3];
                total += d2 * d2 + d3 * d3;
            }
        }
    }
#pragma unroll
    for (int o = 16; o; o >>= 1) total += __shfl_xor_sync(0xffffffffu, total, o);
    __shared__ float red[8];
    if (lane == 0) red[wid] = total;
    __syncthreads();
    if (tid == 0) {
        float s = 0.f;
#pragma unroll
        for (int i = 0; i < 8; i++) s += red[i];
        out[q * WAYS + c] = -s * (1.0f / (float)NTUP);
    }
}

// ---------------- launch ----------------
extern "C" void kernel_launch(void* const* d_in, const int* in_sizes, int n_in,
                              void* d_out, int out_size) {
    const float* sup = (const float*)d_in[0];
    const float* qry = (const float*)d_in[1];
    const float* Wk  = (const float*)d_in[3];
    const float* bk  = (const float*)d_in[4];
    const float* Wv  = (const float*)d_in[5];
    const float* bv  = (const float*)d_in[6];
    const float* lnw = (const float*)d_in[7];
    const float* lnb = (const float*)d_in[8];
    float* out = (float*)d_out;

    // idempotent, capture-safe; called every time (no static guards per harness rules)
    cudaFuncSetAttribute(gemm_main_tc,
                         cudaFuncAttributeMaxDynamicSharedMemorySize, G_SMEM);
    cudaFuncSetAttribute(gemm_scores_tc,
                         cudaFuncAttributeMaxDynamicSharedMemorySize, G_SMEM);
    cudaFuncSetAttribute(proto_logits_tc,
                         cudaFuncAttributeMaxDynamicSharedMemorySize, F_SMEM);

    dim3 gw(DIN / 32, DOUT / 32, 6);
    conv_wt_kernel<<<gw, dim3(32, 8)>>>(Wk, Wv);

    pe_add_kernel<<<XROWS, 256>>>(sup, qry);

    dim3 g1(DOUT / 128, (XROWS + 127) / 128, 6);
    gemm_main_tc<<<g1, 256, G_SMEM>>>();

    tuple_ln_kernel<<<KROWS, 128>>>(bk, bv, lnw, lnb);

    dim3 gv((280 + 31) / 32, DOUT / 32, WAYS);
    vtrans_kernel<<<gv, dim3(32, 8)>>>();

    dim3 g2((SROWS + 127) / 128, (QROWS + 127) / 128);
    gemm_scores_tc<<<g2, 256, G_SMEM>>>();

    dim3 g3(WAYS, QROWS);
    softmax_kernel<<<g3, 128>>>();

    dim3 g4(WAYS, NQ);
    proto_logits_tc<<<g4, 256, F_SMEM>>>(out);
}

// round 8
// speedup vs baseline: 6.7158x; 1.0790x over previous
#include <cuda_runtime.h>
#include <cuda_bf16.h>
#include <math.h>
#include <stdint.h>

// ---------------- problem constants ----------------
#define NQ    200
#define NS    25
#define SEQL  8
#define DIN   2048
#define DOUT  1152
#define NTUP  56
#define WAYS  5
#define SHOTS 5
#define NTOT  (NS + NQ)        // 225
#define XROWS (NTOT * SEQL)    // 1800
#define MROWS (NTOT * 6)       // 1350 packed rows per j in gemm_main
#define SROWS (NS * NTUP)      // 1400
#define QROWS (NQ * NTUP)      // 11200
#define KROWS (NTOT * NTUP)    // 12600

#define SCALE_QK 0.029462782549439477f   // 1/sqrt(1152)

// ---------------- scratch ----------------
__device__ __nv_bfloat16 d_XP[XROWS * DIN];                    // bf16(x + pe)
__device__ __nv_bfloat16 d_Wt[2 * 3 * DOUT * DIN];             // transposed bf16 weights [w][j][n][k]
__device__ float d_Pk[XROWS * 3 * DOUT];
__device__ float d_Pv[XROWS * 3 * DOUT];
__device__ __nv_bfloat16 d_K[KROWS * DOUT];                    // bf16 LN(K)
__device__ float d_V[KROWS * DOUT];                            // fp32 exact V
__device__ __nv_bfloat16 d_Vtt[WAYS * DOUT * 320];             // support V transposed [c][d][320], shot-padded
__device__ float d_S[(size_t)QROWS * SROWS];                   // fp32 scores
__device__ __nv_bfloat16 d_At[(size_t)QROWS * WAYS * 320];     // bf16 attn, shot-padded 5*64

__constant__ int TUP[NTUP][3] = {
 {0,1,2},{0,1,3},{0,1,4},{0,1,5},{0,1,6},{0,1,7},
 {0,2,3},{0,2,4},{0,2,5},{0,2,6},{0,2,7},
 {0,3,4},{0,3,5},{0,3,6},{0,3,7},
 {0,4,5},{0,4,6},{0,4,7},
 {0,5,6},{0,5,7},
 {0,6,7},
 {1,2,3},{1,2,4},{1,2,5},{1,2,6},{1,2,7},
 {1,3,4},{1,3,5},{1,3,6},{1,3,7},
 {1,4,5},{1,4,6},{1,4,7},
 {1,5,6},{1,5,7},
 {1,6,7},
 {2,3,4},{2,3,5},{2,3,6},{2,3,7},
 {2,4,5},{2,4,6},{2,4,7},
 {2,5,6},{2,5,7},
 {2,6,7},
 {3,4,5},{3,4,6},{3,4,7},
 {3,5,6},{3,5,7},
 {3,6,7},
 {4,5,6},{4,5,7},{4,6,7},
 {5,6,7}
};

// ---------------- helpers ----------------
__device__ __forceinline__ void mma16(float* c, const unsigned* a, unsigned b0, unsigned b1) {
    asm volatile(
        "mma.sync.aligned.m16n8k16.row.col.f32.bf16.bf16.f32 "
        "{%0,%1,%2,%3}, {%4,%5,%6,%7}, {%8,%9}, {%0,%1,%2,%3};"
        : "+f"(c[0]), "+f"(c[1]), "+f"(c[2]), "+f"(c[3])
        : "r"(a[0]), "r"(a[1]), "r"(a[2]), "r"(a[3]), "r"(b0), "r"(b1));
}

__device__ __forceinline__ void cpa16(unsigned dst, const void* src, bool pred) {
    int sz = pred ? 16 : 0;
    asm volatile("cp.async.cg.shared.global [%0], [%1], 16, %2;\n"
                 :: "r"(dst), "l"(src), "r"(sz));
}
#define CP_COMMIT() asm volatile("cp.async.commit_group;\n")
#define CP_WAIT(n)  asm volatile("cp.async.wait_group %0;\n" :: "n"(n))

// ---------------- stage A0: transpose + convert W -> d_Wt [w][j][n][k] bf16 ----
__global__ void conv_wt_kernel(const float* __restrict__ Wk,
                               const float* __restrict__ Wv) {
    __shared__ float t[32][33];
    int z = blockIdx.z;
    int w = z / 3, j = z - w * 3;
    const float* __restrict__ W = w ? Wv : Wk;
    int k0 = blockIdx.x * 32, n0 = blockIdx.y * 32;
    int tx = threadIdx.x, ty = threadIdx.y;
#pragma unroll
    for (int r = 0; r < 4; r++) {
        int k = k0 + ty + r * 8;
        t[ty + r * 8][tx] = W[(size_t)(j * DIN + k) * DOUT + n0 + tx];
    }
    __syncthreads();
#pragma unroll
    for (int r = 0; r < 4; r++) {
        int n = n0 + ty + r * 8;
        d_Wt[((size_t)(w * 3 + j) * DOUT + n) * DIN + k0 + tx] =
            __float2bfloat16_rn(t[tx][ty + r * 8]);
    }
}

// ---------------- stage A: x + PE -> bf16 ----------------
__global__ void pe_add_kernel(const float* __restrict__ sup,
                              const float* __restrict__ qry) {
    int row = blockIdx.x;
    int i = row >> 3, l = row & 7;
    const float* src = (i < NS)
        ? sup + ((size_t)i * SEQL + l) * DIN
        : qry + ((size_t)(i - NS) * SEQL + l) * DIN;
    __nv_bfloat16* dst = d_XP + (size_t)row * DIN;
    const float kfac = -9.210340371976184f / (float)DIN;
    for (int d = threadIdx.x; d < DIN; d += blockDim.x) {
        int k2 = d & ~1;
        float arg = (float)l * expf((float)k2 * kfac);
        float pe = ((d & 1) ? cosf(arg) : sinf(arg)) * 0.1f;
        dst[d] = __float2bfloat16_rn(src[d] + pe);
    }
}

// ---------------- stage B: P = XP @ W_blocks (bf16, packed M=1350/j) ----------
// grid (9, 11, 6); block 256 (8 warps, 2m x 4n)
#define G_TS (128 * 36)
#define G_SMEM (4 * G_TS * 4)

__global__ void gemm_main_tc() {
    extern __shared__ unsigned sh[];
    unsigned* As = sh;
    unsigned* Bs = sh + 2 * G_TS;
    unsigned as_base = (unsigned)__cvta_generic_to_shared(As);
    unsigned bs_base = (unsigned)__cvta_generic_to_shared(Bs);

    int z = blockIdx.z;
    int w = z / 3, j = z - w * 3;
    const __nv_bfloat16* __restrict__ Bp = d_Wt + (size_t)(w * 3 + j) * DOUT * DIN;
    float* __restrict__ C = w ? d_Pv : d_Pk;

    int bm = blockIdx.y * 128, bn = blockIdx.x * 128;
    int tid = threadIdx.x, lane = tid & 31, wid = tid >> 5;
    int wm = (wid & 1) * 64, wn = (wid >> 1) * 32;
    int lg = lane >> 2, lr = lane & 3;

    float acc[4][4][4];
#pragma unroll
    for (int mi = 0; mi < 4; mi++)
#pragma unroll
        for (int ni = 0; ni < 4; ni++)
#pragma unroll
            for (int e = 0; e < 4; e++) acc[mi][ni][e] = 0.f;

    auto load_stage = [&](int s, int k0) {
#pragma unroll
        for (int i = 0; i < 4; i++) {
            int e = tid + i * 256;
            int row = e >> 3, ch = e & 7;
            int grow = bm + row;
            bool pa = grow < MROWS;
            int ii = pa ? grow / 6 : 0;
            int ll = pa ? j + (grow - ii * 6) : 0;
            const __nv_bfloat16* ga =
                d_XP + (size_t)(ii * 8 + ll) * DIN + k0 + ch * 8;
            cpa16(as_base + (s * G_TS + row * 36 + ch * 4) * 4, ga, pa);
            const __nv_bfloat16* gb =
                Bp + (size_t)(bn + row) * DIN + k0 + ch * 8;
            cpa16(bs_base + (s * G_TS + row * 36 + ch * 4) * 4, gb, true);
        }
    };

    const int KT = DIN / 64;   // 32
    load_stage(0, 0);
    CP_COMMIT();
    int buf = 0;
    for (int kt = 0; kt < KT; kt++) {
        if (kt + 1 < KT) {
            load_stage(buf ^ 1, (kt + 1) * 64);
            CP_COMMIT();
            CP_WAIT(1);
        } else {
            CP_WAIT(0);
        }
        __syncthreads();
        const unsigned* Aq = As + buf * G_TS;
        const unsigned* Bq = Bs + buf * G_TS;
#pragma unroll
        for (int ks = 0; ks < 4; ks++) {
            int kw = ks * 8;
            unsigned af[4][4];
#pragma unroll
            for (int mi = 0; mi < 4; mi++) {
                int m = wm + mi * 16 + lg;
                af[mi][0] = Aq[m * 36 + kw + lr];
                af[mi][1] = Aq[(m + 8) * 36 + kw + lr];
                af[mi][2] = Aq[m * 36 + kw + lr + 4];
                af[mi][3] = Aq[(m + 8) * 36 + kw + lr + 4];
            }
#pragma unroll
            for (int ni = 0; ni < 4; ni++) {
                int n = wn + ni * 8 + lg;
                unsigned b0 = Bq[n * 36 + kw + lr];
                unsigned b1 = Bq[n * 36 + kw + lr + 4];
#pragma unroll
                for (int mi = 0; mi < 4; mi++)
                    mma16(acc[mi][ni], af[mi], b0, b1);
            }
        }
        __syncthreads();
        buf ^= 1;
    }
#pragma unroll
    for (int mi = 0; mi < 4; mi++) {
        int r0 = bm + wm + mi * 16 + lg;
        int r1 = r0 + 8;
        int i0 = r0 / 6, l0 = j + (r0 - i0 * 6);
        int i1 = r1 / 6, l1 = j + (r1 - i1 * 6);
#pragma unroll
        for (int ni = 0; ni < 4; ni++) {
            int cb = bn + wn + ni * 8 + lr * 2;
            if (r0 < MROWS) {
                float* p = &C[((size_t)(i0 * 8 + l0) * 3 + j) * DOUT + cb];
                p[0] = acc[mi][ni][0]; p[1] = acc[mi][ni][1];
            }
            if (r1 < MROWS) {
                float* p = &C[((size_t)(i1 * 8 + l1) * 3 + j) * DOUT + cb];
                p[0] = acc[mi][ni][2]; p[1] = acc[mi][ni][3];
            }
        }
    }
}

// ---------------- stage C: tuple-sum + bias (+LN for K), float4 ----------------
__global__ void tuple_ln_kernel(const float* __restrict__ bk,
                                const float* __restrict__ bv,
                                const float* __restrict__ lnw,
                                const float* __restrict__ lnb) {
    int it = blockIdx.x;
    int i = it / NTUP, t = it - i * NTUP;
    int l0 = TUP[t][0], l1 = TUP[t][1], l2 = TUP[t][2];
    const float4* pk0 = (const float4*)&d_Pk[((size_t)(i * SEQL + l0) * 3 + 0) * DOUT];
    const float4* pk1 = (const float4*)&d_Pk[((size_t)(i * SEQL + l1) * 3 + 1) * DOUT];
    const float4* pk2 = (const float4*)&d_Pk[((size_t)(i * SEQL + l2) * 3 + 2) * DOUT];
    const float4* pv0 = (const float4*)&d_Pv[((size_t)(i * SEQL + l0) * 3 + 0) * DOUT];
    const float4* pv1 = (const float4*)&d_Pv[((size_t)(i * SEQL + l1) * 3 + 1) * DOUT];
    const float4* pv2 = (const float4*)&d_Pv[((size_t)(i * SEQL + l2) * 3 + 2) * DOUT];
    const float4* bk4 = (const float4*)bk;
    const float4* bv4 = (const float4*)bv;
    const float4* lw4 = (const float4*)lnw;
    const float4* lb4 = (const float4*)lnb;
    float4* v4 = (float4*)&d_V[(size_t)it * DOUT];
    uint2* k2o = (uint2*)&d_K[(size_t)it * DOUT];

    int tid = threadIdx.x;
    float4 kv[3];
    float s = 0.f, sq = 0.f;
#pragma unroll
    for (int e = 0; e < 3; e++) {
        int o4 = tid + e * 128;
        if (o4 < 288) {
            float4 a = pk0[o4], b = pk1[o4], c = pk2[o4], d = bk4[o4];
            float4 v;
            v.x = a.x + b.x + c.x + d.x;
            v.y = a.y + b.y + c.y + d.y;
            v.z = a.z + b.z + c.z + d.z;
            v.w = a.w + b.w + c.w + d.w;
            kv[e] = v;
            s  += v.x + v.y + v.z + v.w;
            sq += v.x * v.x + v.y * v.y + v.z * v.z + v.w * v.w;
            float4 e0 = pv0[o4], e1 = pv1[o4], e2 = pv2[o4], e3 = bv4[o4];
            float4 vv;
            vv.x = e0.x + e1.x + e2.x + e3.x;
            vv.y = e0.y + e1.y + e2.y + e3.y;
            vv.z = e0.z + e1.z + e2.z + e3.z;
            vv.w = e0.w + e1.w + e2.w + e3.w;
            v4[o4] = vv;
        }
    }
#pragma unroll
    for (int o = 16; o; o >>= 1) {
        s  += __shfl_xor_sync(0xffffffffu, s,  o);
        sq += __shfl_xor_sync(0xffffffffu, sq, o);
    }
    __shared__ float ss[4], sqq[4];
    if ((tid & 31) == 0) { ss[tid >> 5] = s; sqq[tid >> 5] = sq; }
    __syncthreads();
    s  = ss[0] + ss[1] + ss[2] + ss[3];
    sq = sqq[0] + sqq[1] + sqq[2] + sqq[3];
    float mean = s * (1.0f / DOUT);
    float var  = sq * (1.0f / DOUT) - mean * mean;
    float rstd = rsqrtf(var + 1e-5f);
#pragma unroll
    for (int e = 0; e < 3; e++) {
        int o4 = tid + e * 128;
        if (o4 < 288) {
            float4 w = lw4[o4], b = lb4[o4], v = kv[e];
            float x0 = (v.x - mean) * rstd * w.x + b.x;
            float x1 = (v.y - mean) * rstd * w.y + b.y;
            float x2 = (v.z - mean) * rstd * w.z + b.z;
            float x3 = (v.w - mean) * rstd * w.w + b.w;
            __nv_bfloat162 lo = __floats2bfloat162_rn(x0, x1);
            __nv_bfloat162 hi = __floats2bfloat162_rn(x2, x3);
            uint2 o2;
            o2.x = *(unsigned*)&lo;
            o2.y = *(unsigned*)&hi;
            k2o[o4] = o2;
        }
    }
}

// ---------------- stage C2: transpose support V -> d_Vtt [c][d][320] bf16 ------
// grid (9 ktiles, 36 dtiles, 5), block (32, 8)
__global__ void vtrans_kernel() {
    __shared__ float t[32][33];
    int c = blockIdx.z;
    int k0 = blockIdx.x * 32, d0 = blockIdx.y * 32;
    int tx = threadIdx.x, ty = threadIdx.y;
#pragma unroll
    for (int r = 0; r < 4; r++) {
        int kc = k0 + ty + r * 8;
        if (kc < 280)
            t[ty + r * 8][tx] = d_V[(size_t)(c * 280 + kc) * DOUT + d0 + tx];
    }
    __syncthreads();
#pragma unroll
    for (int r = 0; r < 4; r++) {
        int d = d0 + ty + r * 8;
        int kc = k0 + tx;
        if (kc < 280) {
            int sh = kc / 56, tt = kc - sh * 56;
            d_Vtt[((size_t)c * DOUT + d) * 320 + sh * 64 + tt] =
                __float2bfloat16_rn(t[tx][ty + r * 8]);
        }
    }
    // zero-fill shot pads (one block per (dtile,c))
    if (blockIdx.x == 0) {
        for (int pp = ty * 32 + tx; pp < 32 * 40; pp += 256) {
            int dd = pp / 40, po = pp - dd * 40;
            int sh = po >> 3, t8 = po & 7;
            d_Vtt[((size_t)c * DOUT + d0 + dd) * 320 + sh * 64 + 56 + t8] =
                __float2bfloat16_rn(0.f);
        }
    }
}

// ---------------- stage D: scores (bf16 m16n8k16, BK=64, 2-stage) -------------
__global__ void gemm_scores_tc() {
    extern __shared__ unsigned sh[];
    unsigned* As = sh;
    unsigned* Bs = sh + 2 * G_TS;
    unsigned as_base = (unsigned)__cvta_generic_to_shared(As);
    unsigned bs_base = (unsigned)__cvta_generic_to_shared(Bs);

    const __nv_bfloat16* __restrict__ A  = d_K + (size_t)SROWS * DOUT;
    const __nv_bfloat16* __restrict__ Bm = d_K;

    int bm = blockIdx.y * 128, bn = blockIdx.x * 128;
    int tid = threadIdx.x, lane = tid & 31, wid = tid >> 5;
    int wm = (wid & 1) * 64, wn = (wid >> 1) * 32;
    int lg = lane >> 2, lr = lane & 3;

    float acc[4][4][4];
#pragma unroll
    for (int mi = 0; mi < 4; mi++)
#pragma unroll
        for (int ni = 0; ni < 4; ni++)
#pragma unroll
            for (int e = 0; e < 4; e++) acc[mi][ni][e] = 0.f;

    auto load_stage = [&](int s, int k0) {
#pragma unroll
        for (int i = 0; i < 4; i++) {
            int e = tid + i * 256;
            int row = e >> 3, ch = e & 7;
            bool pa = (bm + row) < QROWS;
            const __nv_bfloat16* ga =
                A + (size_t)(pa ? bm + row : 0) * DOUT + k0 + ch * 8;
            cpa16(as_base + (s * G_TS + row * 36 + ch * 4) * 4, ga, pa);
            bool pb = (bn + row) < SROWS;
            const __nv_bfloat16* gb =
                Bm + (size_t)(pb ? bn + row : 0) * DOUT + k0 + ch * 8;
            cpa16(bs_base + (s * G_TS + row * 36 + ch * 4) * 4, gb, pb);
        }
    };

    const int KT = DOUT / 64;   // 18
    load_stage(0, 0);
    CP_COMMIT();
    int buf = 0;
    for (int kt = 0; kt < KT; kt++) {
        if (kt + 1 < KT) {
            load_stage(buf ^ 1, (kt + 1) * 64);
            CP_COMMIT();
            CP_WAIT(1);
        } else {
            CP_WAIT(0);
        }
        __syncthreads();
        const unsigned* Aq = As + buf * G_TS;
        const unsigned* Bq = Bs + buf * G_TS;
#pragma unroll
        for (int ks = 0; ks < 4; ks++) {
            int kw = ks * 8;
            unsigned af[4][4];
#pragma unroll
            for (int mi = 0; mi < 4; mi++) {
                int m = wm + mi * 16 + lg;
                af[mi][0] = Aq[m * 36 + kw + lr];
                af[mi][1] = Aq[(m + 8) * 36 + kw + lr];
                af[mi][2] = Aq[m * 36 + kw + lr + 4];
                af[mi][3] = Aq[(m + 8) * 36 + kw + lr + 4];
            }
#pragma unroll
            for (int ni = 0; ni < 4; ni++) {
                int n = wn + ni * 8 + lg;
                unsigned b0 = Bq[n * 36 + kw + lr];
                unsigned b1 = Bq[n * 36 + kw + lr + 4];
#pragma unroll
                for (int mi = 0; mi < 4; mi++)
                    mma16(acc[mi][ni], af[mi], b0, b1);
            }
        }
        __syncthreads();
        buf ^= 1;
    }
#pragma unroll
    for (int mi = 0; mi < 4; mi++) {
        int r0 = bm + wm + mi * 16 + lg;
        int r1 = r0 + 8;
#pragma unroll
        for (int ni = 0; ni < 4; ni++) {
            int cb = bn + wn + ni * 8 + lr * 2;
            if (cb < SROWS) {
                if (r0 < QROWS) {
                    float* p = &d_S[(size_t)r0 * SROWS + cb];
                    p[0] = acc[mi][ni][0] * SCALE_QK;
                    p[1] = acc[mi][ni][1] * SCALE_QK;
                }
                if (r1 < QROWS) {
                    float* p = &d_S[(size_t)r1 * SROWS + cb];
                    p[0] = acc[mi][ni][2] * SCALE_QK;
                    p[1] = acc[mi][ni][3] * SCALE_QK;
                }
            }
        }
    }
}

// ---------------- stage E: segmented softmax, one warp per (row, class) --------
// grid = 7000, block 256 (8 warps)
__global__ void softmax_kernel() {
    int tid = threadIdx.x, wid = tid >> 5, lane = tid & 31;
    int row = blockIdx.x * 8 + wid;            // 0 .. 55999
    int m = row / WAYS, c = row - m * WAYS;
    const float* p = d_S + (size_t)m * SROWS + c * 280;
    __nv_bfloat16* po = d_At + ((size_t)m * WAYS + c) * 320;

    float v[9];
    float mx = -3.4e38f;
#pragma unroll
    for (int e = 0; e < 9; e++) {
        int idx = lane + e * 32;
        if (idx < 280) { v[e] = p[idx]; mx = fmaxf(mx, v[e]); }
        else v[e] = -3.4e38f;
    }
#pragma unroll
    for (int o = 16; o; o >>= 1) mx = fmaxf(mx, __shfl_xor_sync(0xffffffffu, mx, o));

    float sum = 0.f;
#pragma unroll
    for (int e = 0; e < 9; e++) {
        int idx = lane + e * 32;
        if (idx < 280) { v[e] = expf(v[e] - mx); sum += v[e]; }
    }
#pragma unroll
    for (int o = 16; o; o >>= 1) sum += __shfl_xor_sync(0xffffffffu, sum, o);
    float inv = 1.0f / sum;
#pragma unroll
    for (int e = 0; e < 9; e++) {
        int idx = lane + e * 32;
        if (idx < 280) {
            int shd = idx / NTUP, t = idx - shd * NTUP;
            po[shd * 64 + t] = __float2bfloat16_rn(v[e] * inv);
        }
    }
    if (lane < 8) {
#pragma unroll
        for (int shd = 0; shd < SHOTS; shd++)
            po[shd * 64 + 56 + lane] = __float2bfloat16_rn(0.f);
    }
}

// ---------------- stage F: fused proto + logits, 2 queries per CTA -------------
// grid (WAYS, NQ/2), block 256 (8 warps: 4m x 2n over M=128, N=128)
#define F_PW 164                       // u32 words per row (pitch 328 bf16), %32==4
#define F_SMEM (2 * 128 * F_PW * 4)    // attn + cv = 167936 B

__global__ void proto_logits_tc(float* __restrict__ out) {
    extern __shared__ unsigned sh[];
    unsigned* attn_w = sh;             // [128][164] : rows 0..63 q0, 64..127 q0+1
    unsigned* cv_w = sh + 128 * F_PW;  // [128][164] : rows = d within chunk
    unsigned attn_base = (unsigned)__cvta_generic_to_shared(attn_w);
    unsigned cv_base = (unsigned)__cvta_generic_to_shared(cv_w);

    int c = blockIdx.x, q0 = blockIdx.y * 2;
    int tid = threadIdx.x, lane = tid & 31, wid = tid >> 5;
    int wm = (wid & 3) * 16, wn = (wid >> 2) * 64;
    int lg = lane >> 2, lr = lane & 3;

    // load attn for both queries: 128 rows x 40 16B-chunks
    for (int f = tid; f < 128 * 40; f += 256) {
        int rr = f / 40, ch = f - rr * 40;
        int qq = rr >> 6, a = rr & 63;
        if (a < NTUP) {
            const __nv_bfloat16* src =
                d_At + ((size_t)((q0 + qq) * NTUP + a) * WAYS + c) * 320 + ch * 8;
            cpa16(attn_base + (rr * F_PW + ch * 4) * 4, src, true);
        } else {
            *(uint4*)((char*)attn_w + (rr * F_PW + ch * 4) * 4) =
                make_uint4(0, 0, 0, 0);
        }
    }
    CP_COMMIT();

    float total[2] = {0.f, 0.f};
    for (int n0 = 0; n0 < DOUT; n0 += 128) {
        __syncthreads();   // previous chunk's MMA reads of cv done
        // cv tile: rows n (=d), 320 k (shot-padded), 40 chunks per row
        for (int f = tid; f < 128 * 40; f += 256) {
            int n = f / 40, ch = f - n * 40;
            const __nv_bfloat16* src =
                d_Vtt + ((size_t)c * DOUT + n0 + n) * 320 + ch * 8;
            cpa16(cv_base + (n * F_PW + ch * 4) * 4, src, true);
        }
        CP_COMMIT();
        CP_WAIT(0);
        __syncthreads();

        float acc[2][8][4];
#pragma unroll
        for (int mi = 0; mi < 2; mi++)
#pragma unroll
            for (int ni = 0; ni < 8; ni++)
#pragma unroll
                for (int e = 0; e < 4; e++) acc[mi][ni][e] = 0.f;

#pragma unroll
        for (int ks = 0; ks < 20; ks++) {
            int kw = ks * 8;
            unsigned af[2][4];
#pragma unroll
            for (int mi = 0; mi < 2; mi++) {
                int m = mi * 64 + wm + lg;
                af[mi][0] = attn_w[m * F_PW + kw + lr];
                af[mi][1] = attn_w[(m + 8) * F_PW + kw + lr];
                af[mi][2] = attn_w[m * F_PW + kw + lr + 4];
                af[mi][3] = attn_w[(m + 8) * F_PW + kw + lr + 4];
            }
#pragma unroll
            for (int ni = 0; ni < 8; ni++) {
                int nn = wn + ni * 8 + lg;
                unsigned b0 = cv_w[nn * F_PW + kw + lr];
                unsigned b1 = cv_w[nn * F_PW + kw + lr + 4];
                mma16(acc[0][ni], af[0], b0, b1);
                mma16(acc[1][ni], af[1], b0, b1);
            }
        }
        // ||qv - proto||^2 for this d-chunk, per query
        int r0 = wm + lg, r1 = r0 + 8;
#pragma unroll
        for (int mi = 0; mi < 2; mi++) {
            const float* qv0 =
                &d_V[(size_t)((NS + q0 + mi) * NTUP + r0) * DOUT];
            const float* qv1 = qv0 + (size_t)8 * DOUT;
#pragma unroll
            for (int ni = 0; ni < 8; ni++) {
                int col = n0 + wn + ni * 8 + lr * 2;
                if (r0 < NTUP) {
                    float d0 = qv0[col]     - acc[mi][ni][0];
                    float d1 = qv0[col + 1] - acc[mi][ni][1];
                    total[mi] += d0 * d0 + d1 * d1;
                }
                if (r1 < NTUP) {
                    float d2 = qv1[col]     - acc[mi][ni][2];
                    float d3 = qv1[col + 1] - acc[mi][ni][3];
                    total[mi] += d2 * d2 + d3 * d3;
                }
            }
        }
    }
#pragma unroll
    for (int o = 16; o; o >>= 1) {
        total[0] += __shfl_xor_sync(0xffffffffu, total[0], o);
        total[1] += __shfl_xor_sync(0xffffffffu, total[1], o);
    }
    __syncthreads();
    float* red = (float*)attn_w;
    if (lane == 0) { red[wid * 2] = total[0]; red[wid * 2 + 1] = total[1]; }
    __syncthreads();
    if (tid < 2) {
        float s = 0.f;
#pragma unroll
        for (int i = 0; i < 8; i++) s += red[i * 2 + tid];
        out[(q0 + tid) * WAYS + c] = -s * (1.0f / (float)NTUP);
    }
}

// ---------------- launch ----------------
extern "C" void kernel_launch(void* const* d_in, const int* in_sizes, int n_in,
                              void* d_out, int out_size) {
    const float* sup = (const float*)d_in[0];
    const float* qry = (const float*)d_in[1];
    const float* Wk  = (const float*)d_in[3];
    const float* bk  = (const float*)d_in[4];
    const float* Wv  = (const float*)d_in[5];
    const float* bv  = (const float*)d_in[6];
    const float* lnw = (const float*)d_in[7];
    const float* lnb = (const float*)d_in[8];
    float* out = (float*)d_out;

    cudaFuncSetAttribute(gemm_main_tc,
                         cudaFuncAttributeMaxDynamicSharedMemorySize, G_SMEM);
    cudaFuncSetAttribute(gemm_scores_tc,
                         cudaFuncAttributeMaxDynamicSharedMemorySize, G_SMEM);
    cudaFuncSetAttribute(proto_logits_tc,
                         cudaFuncAttributeMaxDynamicSharedMemorySize, F_SMEM);

    dim3 gw(DIN / 32, DOUT / 32, 6);
    conv_wt_kernel<<<gw, dim3(32, 8)>>>(Wk, Wv);

    pe_add_kernel<<<XROWS, 256>>>(sup, qry);

    dim3 g1(DOUT / 128, (MROWS + 127) / 128, 6);
    gemm_main_tc<<<g1, 256, G_SMEM>>>();

    tuple_ln_kernel<<<KROWS, 128>>>(bk, bv, lnw, lnb);

    dim3 gv((280 + 31) / 32, DOUT / 32, WAYS);
    vtrans_kernel<<<gv, dim3(32, 8)>>>();

    dim3 g2((SROWS + 127) / 128, (QROWS + 127) / 128);
    gemm_scores_tc<<<g2, 256, G_SMEM>>>();

    softmax_kernel<<<(QROWS * WAYS) / 8, 256>>>();

    dim3 g4(WAYS, NQ / 2);
    proto_logits_tc<<<g4, 256, F_SMEM>>>(out);
}

// round 10
// speedup vs baseline: 7.2680x; 1.0822x over previous
#include <cuda_runtime.h>
#include <cuda_bf16.h>
#include <math.h>
#include <stdint.h>

// ---------------- problem constants ----------------
#define NQ    200
#define NS    25
#define SEQL  8
#define DIN   2048
#define DOUT  1152
#define NTUP  56
#define WAYS  5
#define SHOTS 5
#define NTOT  (NS + NQ)        // 225
#define XROWS (NTOT * SEQL)    // 1800
#define MROWS (NTOT * 6)       // 1350 packed rows per j in gemm_main
#define SROWS (NS * NTUP)      // 1400
#define QROWS (NQ * NTUP)      // 11200
#define KROWS (NTOT * NTUP)    // 12600

#define SCALE_QK 0.029462782549439477f   // 1/sqrt(1152)

// ---------------- scratch ----------------
__device__ __nv_bfloat16 d_XP[XROWS * DIN];                    // bf16(x + pe)
__device__ __nv_bfloat16 d_Wt[2 * 3 * DOUT * DIN];             // transposed bf16 weights [w][j][n][k]
__device__ float d_Pk[XROWS * 3 * DOUT];
__device__ float d_Pv[XROWS * 3 * DOUT];
__device__ __nv_bfloat16 d_K[KROWS * DOUT];                    // bf16 LN(K)
__device__ float d_V[KROWS * DOUT];                            // fp32 exact V
__device__ __nv_bfloat16 d_Vtt[WAYS * DOUT * 320];             // support V transposed [c][d][320], shot-padded
__device__ float d_S[(size_t)QROWS * SROWS];                   // fp32 scores
__device__ __nv_bfloat16 d_At[(size_t)QROWS * WAYS * 320];     // bf16 attn, shot-padded 5*64

__constant__ int TUP[NTUP][3] = {
 {0,1,2},{0,1,3},{0,1,4},{0,1,5},{0,1,6},{0,1,7},
 {0,2,3},{0,2,4},{0,2,5},{0,2,6},{0,2,7},
 {0,3,4},{0,3,5},{0,3,6},{0,3,7},
 {0,4,5},{0,4,6},{0,4,7},
 {0,5,6},{0,5,7},
 {0,6,7},
 {1,2,3},{1,2,4},{1,2,5},{1,2,6},{1,2,7},
 {1,3,4},{1,3,5},{1,3,6},{1,3,7},
 {1,4,5},{1,4,6},{1,4,7},
 {1,5,6},{1,5,7},
 {1,6,7},
 {2,3,4},{2,3,5},{2,3,6},{2,3,7},
 {2,4,5},{2,4,6},{2,4,7},
 {2,5,6},{2,5,7},
 {2,6,7},
 {3,4,5},{3,4,6},{3,4,7},
 {3,5,6},{3,5,7},
 {3,6,7},
 {4,5,6},{4,5,7},{4,6,7},
 {5,6,7}
};

// ---------------- helpers ----------------
__device__ __forceinline__ void mma16(float* c, const unsigned* a, unsigned b0, unsigned b1) {
    asm volatile(
        "mma.sync.aligned.m16n8k16.row.col.f32.bf16.bf16.f32 "
        "{%0,%1,%2,%3}, {%4,%5,%6,%7}, {%8,%9}, {%0,%1,%2,%3};"
        : "+f"(c[0]), "+f"(c[1]), "+f"(c[2]), "+f"(c[3])
        : "r"(a[0]), "r"(a[1]), "r"(a[2]), "r"(a[3]), "r"(b0), "r"(b1));
}

__device__ __forceinline__ void cpa16(unsigned dst, const void* src, bool pred) {
    int sz = pred ? 16 : 0;
    asm volatile("cp.async.cg.shared.global [%0], [%1], 16, %2;\n"
                 :: "r"(dst), "l"(src), "r"(sz));
}
#define CP_COMMIT() asm volatile("cp.async.commit_group;\n")
#define CP_WAIT(n)  asm volatile("cp.async.wait_group %0;\n" :: "n"(n))

// ---------------- stage A0: transpose + convert W -> d_Wt [w][j][n][k] bf16 ----
__global__ void conv_wt_kernel(const float* __restrict__ Wk,
                               const float* __restrict__ Wv) {
    __shared__ float t[32][33];
    int z = blockIdx.z;
    int w = z / 3, j = z - w * 3;
    const float* __restrict__ W = w ? Wv : Wk;
    int k0 = blockIdx.x * 32, n0 = blockIdx.y * 32;
    int tx = threadIdx.x, ty = threadIdx.y;
#pragma unroll
    for (int r = 0; r < 4; r++) {
        int k = k0 + ty + r * 8;
        t[ty + r * 8][tx] = W[(size_t)(j * DIN + k) * DOUT + n0 + tx];
    }
    __syncthreads();
#pragma unroll
    for (int r = 0; r < 4; r++) {
        int n = n0 + ty + r * 8;
        d_Wt[((size_t)(w * 3 + j) * DOUT + n) * DIN + k0 + tx] =
            __float2bfloat16_rn(t[tx][ty + r * 8]);
    }
}

// ---------------- stage A: x + PE -> bf16 ----------------
__global__ void pe_add_kernel(const float* __restrict__ sup,
                              const float* __restrict__ qry) {
    int row = blockIdx.x;
    int i = row >> 3, l = row & 7;
    const float* src = (i < NS)
        ? sup + ((size_t)i * SEQL + l) * DIN
        : qry + ((size_t)(i - NS) * SEQL + l) * DIN;
    __nv_bfloat16* dst = d_XP + (size_t)row * DIN;
    const float kfac = -9.210340371976184f / (float)DIN;
    for (int d = threadIdx.x; d < DIN; d += blockDim.x) {
        int k2 = d & ~1;
        float arg = (float)l * expf((float)k2 * kfac);
        float pe = ((d & 1) ? cosf(arg) : sinf(arg)) * 0.1f;
        dst[d] = __float2bfloat16_rn(src[d] + pe);
    }
}

// ---------------- stage B: P = XP @ W_blocks (bf16, packed M=1350/j) ----------
// grid (9, 11, 6); block 128 (4 warps, 2m x 2n, each 64x64)
#define G_TS (128 * 36)
#define G_SMEM (4 * G_TS * 4)

__global__ void __launch_bounds__(128) gemm_main_tc() {
    extern __shared__ unsigned sh[];
    unsigned* As = sh;
    unsigned* Bs = sh + 2 * G_TS;
    unsigned as_base = (unsigned)__cvta_generic_to_shared(As);
    unsigned bs_base = (unsigned)__cvta_generic_to_shared(Bs);

    int z = blockIdx.z;
    int w = z / 3, j = z - w * 3;
    const __nv_bfloat16* __restrict__ Bp = d_Wt + (size_t)(w * 3 + j) * DOUT * DIN;
    float* __restrict__ C = w ? d_Pv : d_Pk;

    int bm = blockIdx.y * 128, bn = blockIdx.x * 128;
    int tid = threadIdx.x, lane = tid & 31, wid = tid >> 5;
    int wm = (wid & 1) * 64, wn = (wid >> 1) * 64;
    int lg = lane >> 2, lr = lane & 3;

    float acc[4][8][4];
#pragma unroll
    for (int mi = 0; mi < 4; mi++)
#pragma unroll
        for (int ni = 0; ni < 8; ni++)
#pragma unroll
            for (int e = 0; e < 4; e++) acc[mi][ni][e] = 0.f;

    auto load_stage = [&](int s, int k0) {
#pragma unroll
        for (int i = 0; i < 8; i++) {
            int e = tid + i * 128;
            int row = e >> 3, ch = e & 7;           // 8 x 16B chunks per row of 64 bf16
            int grow = bm + row;
            bool pa = grow < MROWS;
            int ii = pa ? grow / 6 : 0;
            int ll = pa ? j + (grow - ii * 6) : 0;
            const __nv_bfloat16* ga =
                d_XP + (size_t)(ii * 8 + ll) * DIN + k0 + ch * 8;
            cpa16(as_base + (s * G_TS + row * 36 + ch * 4) * 4, ga, pa);
            const __nv_bfloat16* gb =
                Bp + (size_t)(bn + row) * DIN + k0 + ch * 8;
            cpa16(bs_base + (s * G_TS + row * 36 + ch * 4) * 4, gb, true);
        }
    };

    const int KT = DIN / 64;   // 32
    load_stage(0, 0);
    CP_COMMIT();
    int buf = 0;
    for (int kt = 0; kt < KT; kt++) {
        if (kt + 1 < KT) {
            load_stage(buf ^ 1, (kt + 1) * 64);
            CP_COMMIT();
            CP_WAIT(1);
        } else {
            CP_WAIT(0);
        }
        __syncthreads();
        const unsigned* Aq = As + buf * G_TS;
        const unsigned* Bq = Bs + buf * G_TS;
#pragma unroll
        for (int ks = 0; ks < 4; ks++) {
            int kw = ks * 8;
            unsigned af[4][4];
#pragma unroll
            for (int mi = 0; mi < 4; mi++) {
                int m = wm + mi * 16 + lg;
                af[mi][0] = Aq[m * 36 + kw + lr];
                af[mi][1] = Aq[(m + 8) * 36 + kw + lr];
                af[mi][2] = Aq[m * 36 + kw + lr + 4];
                af[mi][3] = Aq[(m + 8) * 36 + kw + lr + 4];
            }
#pragma unroll
            for (int ni = 0; ni < 8; ni++) {
                int n = wn + ni * 8 + lg;
                unsigned b0 = Bq[n * 36 + kw + lr];
                unsigned b1 = Bq[n * 36 + kw + lr + 4];
#pragma unroll
                for (int mi = 0; mi < 4; mi++)
                    mma16(acc[mi][ni], af[mi], b0, b1);
            }
        }
        __syncthreads();
        buf ^= 1;
    }
#pragma unroll
    for (int mi = 0; mi < 4; mi++) {
        int r0 = bm + wm + mi * 16 + lg;
        int r1 = r0 + 8;
        int i0 = r0 / 6, l0 = j + (r0 - i0 * 6);
        int i1 = r1 / 6, l1 = j + (r1 - i1 * 6);
#pragma unroll
        for (int ni = 0; ni < 8; ni++) {
            int cb = bn + wn + ni * 8 + lr * 2;
            if (r0 < MROWS) {
                float* p = &C[((size_t)(i0 * 8 + l0) * 3 + j) * DOUT + cb];
                p[0] = acc[mi][ni][0]; p[1] = acc[mi][ni][1];
            }
            if (r1 < MROWS) {
                float* p = &C[((size_t)(i1 * 8 + l1) * 3 + j) * DOUT + cb];
                p[0] = acc[mi][ni][2]; p[1] = acc[mi][ni][3];
            }
        }
    }
}

// ---------------- stage C: tuple-sum + bias (+LN for K), float4 ----------------
__global__ void tuple_ln_kernel(const float* __restrict__ bk,
                                const float* __restrict__ bv,
                                const float* __restrict__ lnw,
                                const float* __restrict__ lnb) {
    int it = blockIdx.x;
    int i = it / NTUP, t = it - i * NTUP;
    int l0 = TUP[t][0], l1 = TUP[t][1], l2 = TUP[t][2];
    const float4* pk0 = (const float4*)&d_Pk[((size_t)(i * SEQL + l0) * 3 + 0) * DOUT];
    const float4* pk1 = (const float4*)&d_Pk[((size_t)(i * SEQL + l1) * 3 + 1) * DOUT];
    const float4* pk2 = (const float4*)&d_Pk[((size_t)(i * SEQL + l2) * 3 + 2) * DOUT];
    const float4* pv0 = (const float4*)&d_Pv[((size_t)(i * SEQL + l0) * 3 + 0) * DOUT];
    const float4* pv1 = (const float4*)&d_Pv[((size_t)(i * SEQL + l1) * 3 + 1) * DOUT];
    const float4* pv2 = (const float4*)&d_Pv[((size_t)(i * SEQL + l2) * 3 + 2) * DOUT];
    const float4* bk4 = (const float4*)bk;
    const float4* bv4 = (const float4*)bv;
    const float4* lw4 = (const float4*)lnw;
    const float4* lb4 = (const float4*)lnb;
    float4* v4 = (float4*)&d_V[(size_t)it * DOUT];
    uint2* k2o = (uint2*)&d_K[(size_t)it * DOUT];

    int tid = threadIdx.x;
    float4 kv[3];
    float s = 0.f, sq = 0.f;
#pragma unroll
    for (int e = 0; e < 3; e++) {
        int o4 = tid + e * 128;
        if (o4 < 288) {
            float4 a = pk0[o4], b = pk1[o4], c = pk2[o4], d = bk4[o4];
            float4 v;
            v.x = a.x + b.x + c.x + d.x;
            v.y = a.y + b.y + c.y + d.y;
            v.z = a.z + b.z + c.z + d.z;
            v.w = a.w + b.w + c.w + d.w;
            kv[e] = v;
            s  += v.x + v.y + v.z + v.w;
            sq += v.x * v.x + v.y * v.y + v.z * v.z + v.w * v.w;
            float4 e0 = pv0[o4], e1 = pv1[o4], e2 = pv2[o4], e3 = bv4[o4];
            float4 vv;
            vv.x = e0.x + e1.x + e2.x + e3.x;
            vv.y = e0.y + e1.y + e2.y + e3.y;
            vv.z = e0.z + e1.z + e2.z + e3.z;
            vv.w = e0.w + e1.w + e2.w + e3.w;
            v4[o4] = vv;
        }
    }
#pragma unroll
    for (int o = 16; o; o >>= 1) {
        s  += __shfl_xor_sync(0xffffffffu, s,  o);
        sq += __shfl_xor_sync(0xffffffffu, sq, o);
    }
    __shared__ float ss[4], sqq[4];
    if ((tid & 31) == 0) { ss[tid >> 5] = s; sqq[tid >> 5] = sq; }
    __syncthreads();
    s  = ss[0] + ss[1] + ss[2] + ss[3];
    sq = sqq[0] + sqq[1] + sqq[2] + sqq[3];
    float mean = s * (1.0f / DOUT);
    float var  = sq * (1.0f / DOUT) - mean * mean;
    float rstd = rsqrtf(var + 1e-5f);
#pragma unroll
    for (int e = 0; e < 3; e++) {
        int o4 = tid + e * 128;
        if (o4 < 288) {
            float4 w = lw4[o4], b = lb4[o4], v = kv[e];
            float x0 = (v.x - mean) * rstd * w.x + b.x;
            float x1 = (v.y - mean) * rstd * w.y + b.y;
            float x2 = (v.z - mean) * rstd * w.z + b.z;
            float x3 = (v.w - mean) * rstd * w.w + b.w;
            __nv_bfloat162 lo = __floats2bfloat162_rn(x0, x1);
            __nv_bfloat162 hi = __floats2bfloat162_rn(x2, x3);
            uint2 o2;
            o2.x = *(unsigned*)&lo;
            o2.y = *(unsigned*)&hi;
            k2o[o4] = o2;
        }
    }
}

// ---------------- stage C2: transpose support V -> d_Vtt [c][d][320] bf16 ------
__global__ void vtrans_kernel() {
    __shared__ float t[32][33];
    int c = blockIdx.z;
    int k0 = blockIdx.x * 32, d0 = blockIdx.y * 32;
    int tx = threadIdx.x, ty = threadIdx.y;
#pragma unroll
    for (int r = 0; r < 4; r++) {
        int kc = k0 + ty + r * 8;
        if (kc < 280)
            t[ty + r * 8][tx] = d_V[(size_t)(c * 280 + kc) * DOUT + d0 + tx];
    }
    __syncthreads();
#pragma unroll
    for (int r = 0; r < 4; r++) {
        int d = d0 + ty + r * 8;
        int kc = k0 + tx;
        if (kc < 280) {
            int sh = kc / 56, tt = kc - sh * 56;
            d_Vtt[((size_t)c * DOUT + d) * 320 + sh * 64 + tt] =
                __float2bfloat16_rn(t[tx][ty + r * 8]);
        }
    }
    if (blockIdx.x == 0) {
        for (int pp = ty * 32 + tx; pp < 32 * 40; pp += 256) {
            int dd = pp / 40, po = pp - dd * 40;
            int sh = po >> 3, t8 = po & 7;
            d_Vtt[((size_t)c * DOUT + d0 + dd) * 320 + sh * 64 + 56 + t8] =
                __float2bfloat16_rn(0.f);
        }
    }
}

// ---------------- stage D: scores (bf16, 64x64 warp tiles, BK=64, 2-stage) ----
// grid (11, 88); block 128
__global__ void __launch_bounds__(128) gemm_scores_tc() {
    extern __shared__ unsigned sh[];
    unsigned* As = sh;
    unsigned* Bs = sh + 2 * G_TS;
    unsigned as_base = (unsigned)__cvta_generic_to_shared(As);
    unsigned bs_base = (unsigned)__cvta_generic_to_shared(Bs);

    const __nv_bfloat16* __restrict__ A  = d_K + (size_t)SROWS * DOUT;
    const __nv_bfloat16* __restrict__ Bm = d_K;

    int bm = blockIdx.y * 128, bn = blockIdx.x * 128;
    int tid = threadIdx.x, lane = tid & 31, wid = tid >> 5;
    int wm = (wid & 1) * 64, wn = (wid >> 1) * 64;
    int lg = lane >> 2, lr = lane & 3;

    float acc[4][8][4];
#pragma unroll
    for (int mi = 0; mi < 4; mi++)
#pragma unroll
        for (int ni = 0; ni < 8; ni++)
#pragma unroll
            for (int e = 0; e < 4; e++) acc[mi][ni][e] = 0.f;

    auto load_stage = [&](int s, int k0) {
#pragma unroll
        for (int i = 0; i < 8; i++) {
            int e = tid + i * 128;
            int row = e >> 3, ch = e & 7;
            bool pa = (bm + row) < QROWS;
            const __nv_bfloat16* ga =
                A + (size_t)(pa ? bm + row : 0) * DOUT + k0 + ch * 8;
            cpa16(as_base + (s * G_TS + row * 36 + ch * 4) * 4, ga, pa);
            bool pb = (bn + row) < SROWS;
            const __nv_bfloat16* gb =
                Bm + (size_t)(pb ? bn + row : 0) * DOUT + k0 + ch * 8;
            cpa16(bs_base + (s * G_TS + row * 36 + ch * 4) * 4, gb, pb);
        }
    };

    const int KT = DOUT / 64;   // 18
    load_stage(0, 0);
    CP_COMMIT();
    int buf = 0;
    for (int kt = 0; kt < KT; kt++) {
        if (kt + 1 < KT) {
            load_stage(buf ^ 1, (kt + 1) * 64);
            CP_COMMIT();
            CP_WAIT(1);
        } else {
            CP_WAIT(0);
        }
        __syncthreads();
        const unsigned* Aq = As + buf * G_TS;
        const unsigned* Bq = Bs + buf * G_TS;
#pragma unroll
        for (int ks = 0; ks < 4; ks++) {
            int kw = ks * 8;
            unsigned af[4][4];
#pragma unroll
            for (int mi = 0; mi < 4; mi++) {
                int m = wm + mi * 16 + lg;
                af[mi][0] = Aq[m * 36 + kw + lr];
                af[mi][1] = Aq[(m + 8) * 36 + kw + lr];
                af[mi][2] = Aq[m * 36 + kw + lr + 4];
                af[mi][3] = Aq[(m + 8) * 36 + kw + lr + 4];
            }
#pragma unroll
            for (int ni = 0; ni < 8; ni++) {
                int n = wn + ni * 8 + lg;
                unsigned b0 = Bq[n * 36 + kw + lr];
                unsigned b1 = Bq[n * 36 + kw + lr + 4];
#pragma unroll
                for (int mi = 0; mi < 4; mi++)
                    mma16(acc[mi][ni], af[mi], b0, b1);
            }
        }
        __syncthreads();
        buf ^= 1;
    }
#pragma unroll
    for (int mi = 0; mi < 4; mi++) {
        int r0 = bm + wm + mi * 16 + lg;
        int r1 = r0 + 8;
#pragma unroll
        for (int ni = 0; ni < 8; ni++) {
            int cb = bn + wn + ni * 8 + lr * 2;
            if (cb < SROWS) {
                if (r0 < QROWS) {
                    float* p = &d_S[(size_t)r0 * SROWS + cb];
                    p[0] = acc[mi][ni][0] * SCALE_QK;
                    p[1] = acc[mi][ni][1] * SCALE_QK;
                }
                if (r1 < QROWS) {
                    float* p = &d_S[(size_t)r1 * SROWS + cb];
                    p[0] = acc[mi][ni][2] * SCALE_QK;
                    p[1] = acc[mi][ni][3] * SCALE_QK;
                }
            }
        }
    }
}

// ---------------- stage E: segmented softmax, one warp per (row, class) --------
__global__ void softmax_kernel() {
    int tid = threadIdx.x, wid = tid >> 5, lane = tid & 31;
    int row = blockIdx.x * 8 + wid;
    int m = row / WAYS, c = row - m * WAYS;
    const float* p = d_S + (size_t)m * SROWS + c * 280;
    __nv_bfloat16* po = d_At + ((size_t)m * WAYS + c) * 320;

    float v[9];
    float mx = -3.4e38f;
#pragma unroll
    for (int e = 0; e < 9; e++) {
        int idx = lane + e * 32;
        if (idx < 280) { v[e] = p[idx]; mx = fmaxf(mx, v[e]); }
        else v[e] = -3.4e38f;
    }
#pragma unroll
    for (int o = 16; o; o >>= 1) mx = fmaxf(mx, __shfl_xor_sync(0xffffffffu, mx, o));

    float sum = 0.f;
#pragma unroll
    for (int e = 0; e < 9; e++) {
        int idx = lane + e * 32;
        if (idx < 280) { v[e] = expf(v[e] - mx); sum += v[e]; }
    }
#pragma unroll
    for (int o = 16; o; o >>= 1) sum += __shfl_xor_sync(0xffffffffu, sum, o);
    float inv = 1.0f / sum;
#pragma unroll
    for (int e = 0; e < 9; e++) {
        int idx = lane + e * 32;
        if (idx < 280) {
            int shd = idx / NTUP, t = idx - shd * NTUP;
            po[shd * 64 + t] = __float2bfloat16_rn(v[e] * inv);
        }
    }
    if (lane < 8) {
#pragma unroll
        for (int shd = 0; shd < SHOTS; shd++)
            po[shd * 64 + 56 + lane] = __float2bfloat16_rn(0.f);
    }
}

// ---------------- stage F: fused proto + logits, 2 queries per CTA -------------
// grid (WAYS, NQ/2), block 256 (8 warps: 4m x 2n over M=128, N=128)
#define F_PW 164                       // u32 words per row (pitch 328 bf16), %32==4
#define F_SMEM (2 * 128 * F_PW * 4)    // attn + cv = 167936 B

__global__ void proto_logits_tc(float* __restrict__ out) {
    extern __shared__ unsigned sh[];
    unsigned* attn_w = sh;             // [128][164] : rows 0..63 q0, 64..127 q0+1
    unsigned* cv_w = sh + 128 * F_PW;  // [128][164] : rows = d within chunk
    unsigned attn_base = (unsigned)__cvta_generic_to_shared(attn_w);
    unsigned cv_base = (unsigned)__cvta_generic_to_shared(cv_w);

    int c = blockIdx.x, q0 = blockIdx.y * 2;
    int tid = threadIdx.x, lane = tid & 31, wid = tid >> 5;
    int wm = (wid & 3) * 16, wn = (wid >> 2) * 64;
    int lg = lane >> 2, lr = lane & 3;

    // load attn for both queries: 128 rows x 40 16B-chunks
    for (int f = tid; f < 128 * 40; f += 256) {
        int rr = f / 40, ch = f - rr * 40;
        int qq = rr >> 6, a = rr & 63;
        if (a < NTUP) {
            const __nv_bfloat16* src =
                d_At + ((size_t)((q0 + qq) * NTUP + a) * WAYS + c) * 320 + ch * 8;
            cpa16(attn_base + (rr * F_PW + ch * 4) * 4, src, true);
        } else {
            *(uint4*)((char*)attn_w + (rr * F_PW + ch * 4) * 4) =
                make_uint4(0, 0, 0, 0);
        }
    }
    CP_COMMIT();

    float total[2] = {0.f, 0.f};
    for (int n0 = 0; n0 < DOUT; n0 += 128) {
        __syncthreads();   // previous chunk's MMA reads of cv done
        for (int f = tid; f < 128 * 40; f += 256) {
            int n = f / 40, ch = f - n * 40;
            const __nv_bfloat16* src =
                d_Vtt + ((size_t)c * DOUT + n0 + n) * 320 + ch * 8;
            cpa16(cv_base + (n * F_PW + ch * 4) * 4, src, true);
        }
        CP_COMMIT();
        CP_WAIT(0);
        __syncthreads();

        float acc[2][8][4];
#pragma unroll
        for (int mi = 0; mi < 2; mi++)
#pragma unroll
            for (int ni = 0; ni < 8; ni++)
#pragma unroll
                for (int e = 0; e < 4; e++) acc[mi][ni][e] = 0.f;

#pragma unroll
        for (int ks = 0; ks < 20; ks++) {
            int kw = ks * 8;
            unsigned af[2][4];
#pragma unroll
            for (int mi = 0; mi < 2; mi++) {
                int m = mi * 64 + wm + lg;
                af[mi][0] = attn_w[m * F_PW + kw + lr];
                af[mi][1] = attn_w[(m + 8) * F_PW + kw + lr];
                af[mi][2] = attn_w[m * F_PW + kw + lr + 4];
                af[mi][3] = attn_w[(m + 8) * F_PW + kw + lr + 4];
            }
#pragma unroll
            for (int ni = 0; ni < 8; ni++) {
                int nn = wn + ni * 8 + lg;
                unsigned b0 = cv_w[nn * F_PW + kw + lr];
                unsigned b1 = cv_w[nn * F_PW + kw + lr + 4];
                mma16(acc[0][ni], af[0], b0, b1);
                mma16(acc[1][ni], af[1], b0, b1);
            }
        }
        int r0 = wm + lg, r1 = r0 + 8;
#pragma unroll
        for (int mi = 0; mi < 2; mi++) {
            const float* qv0 =
                &d_V[(size_t)((NS + q0 + mi) * NTUP + r0) * DOUT];
            const float* qv1 = qv0 + (size_t)8 * DOUT;
#pragma unroll
            for (int ni = 0; ni < 8; ni++) {
                int col = n0 + wn + ni * 8 + lr * 2;
                if (r0 < NTUP) {
                    float d0 = qv0[col]     - acc[mi][ni][0];
                    float d1 = qv0[col + 1] - acc[mi][ni][1];
                    total[mi] += d0 * d0 + d1 * d1;
                }
                if (r1 < NTUP) {
                    float d2 = qv1[col]     - acc[mi][ni][2];
                    float d3 = qv1[col + 1] - acc[mi][ni][3];
                    total[mi] += d2 * d2 + d3 * d3;
                }
            }
        }
    }
#pragma unroll
    for (int o = 16; o; o >>= 1) {
        total[0] += __shfl_xor_sync(0xffffffffu, total[0], o);
        total[1] += __shfl_xor_sync(0xffffffffu, total[1], o);
    }
    __syncthreads();
    float* red = (float*)attn_w;
    if (lane == 0) { red[wid * 2] = total[0]; red[wid * 2 + 1] = total[1]; }
    __syncthreads();
    if (tid < 2) {
        float s = 0.f;
#pragma unroll
        for (int i = 0; i < 8; i++) s += red[i * 2 + tid];
        out[(q0 + tid) * WAYS + c] = -s * (1.0f / (float)NTUP);
    }
}

// ---------------- launch ----------------
extern "C" void kernel_launch(void* const* d_in, const int* in_sizes, int n_in,
                              void* d_out, int out_size) {
    const float* sup = (const float*)d_in[0];
    const float* qry = (const float*)d_in[1];
    const float* Wk  = (const float*)d_in[3];
    const float* bk  = (const float*)d_in[4];
    const float* Wv  = (const float*)d_in[5];
    const float* bv  = (const float*)d_in[6];
    const float* lnw = (const float*)d_in[7];
    const float* lnb = (const float*)d_in[8];
    float* out = (float*)d_out;

    cudaFuncSetAttribute(gemm_main_tc,
                         cudaFuncAttributeMaxDynamicSharedMemorySize, G_SMEM);
    cudaFuncSetAttribute(gemm_scores_tc,
                         cudaFuncAttributeMaxDynamicSharedMemorySize, G_SMEM);
    cudaFuncSetAttribute(proto_logits_tc,
                         cudaFuncAttributeMaxDynamicSharedMemorySize, F_SMEM);

    dim3 gw(DIN / 32, DOUT / 32, 6);
    conv_wt_kernel<<<gw, dim3(32, 8)>>>(Wk, Wv);

    pe_add_kernel<<<XROWS, 256>>>(sup, qry);

    dim3 g1(DOUT / 128, (MROWS + 127) / 128, 6);
    gemm_main_tc<<<g1, 128, G_SMEM>>>();

    tuple_ln_kernel<<<KROWS, 128>>>(bk, bv, lnw, lnb);

    dim3 gv((280 + 31) / 32, DOUT / 32, WAYS);
    vtrans_kernel<<<gv, dim3(32, 8)>>>();

    dim3 g2((SROWS + 127) / 128, (QROWS + 127) / 128);
    gemm_scores_tc<<<g2, 128, G_SMEM>>>();

    softmax_kernel<<<(QROWS * WAYS) / 8, 256>>>();

    dim3 g4(WAYS, NQ / 2);
    proto_logits_tc<<<g4, 256, F_SMEM>>>(out);
}